// round 2
// baseline (speedup 1.0000x reference)
#include <cuda_runtime.h>

// Problem constants (fixed-shape problem)
#define NN 50000
#define HH 128
#define EE 800000
#define AA 16
#define TT 4
#define HA 144            // H + A
#define TILE_E 64
#define XS_STRIDE 65      // padded row stride for transposed x/hidden tiles

// ---------------- device scratch (no allocations allowed) ----------------
__device__ float g_msg[NN * HH];          // scatter-add target [N,H]
__device__ int   g_bucket[EE];            // edge ids sorted by type
__device__ int   g_cnt[TT];
__device__ int   g_cur[TT];
__device__ int   g_off[TT + 1];
__device__ int   g_tileBase[TT + 1];
__device__ float g_wihT[HH * 3 * HH];     // w_ih transposed to [k][gate]
__device__ float g_whhT[HH * 3 * HH];

// ---------------- utility kernels ----------------
__global__ void k_zero() {
    int idx = blockIdx.x * blockDim.x + threadIdx.x;
    int stride = gridDim.x * blockDim.x;
    float4* p = reinterpret_cast<float4*>(g_msg);
    int total4 = NN * HH / 4;
    float4 z = make_float4(0.f, 0.f, 0.f, 0.f);
    for (int i = idx; i < total4; i += stride) p[i] = z;
    if (idx < TT) g_cnt[idx] = 0;
}

__global__ void k_transpose(const float* __restrict__ wih,
                            const float* __restrict__ whh) {
    int idx = blockIdx.x * blockDim.x + threadIdx.x;
    if (idx < HH * 3 * HH) {
        int k = idx / (3 * HH);
        int g = idx % (3 * HH);
        g_wihT[idx] = wih[g * HH + k];
        g_whhT[idx] = whh[g * HH + k];
    }
}

__global__ void k_hist(const int* __restrict__ et, int E) {
    __shared__ int c[TT];
    if (threadIdx.x < TT) c[threadIdx.x] = 0;
    __syncthreads();
    int i = blockIdx.x * blockDim.x + threadIdx.x;
    if (i < E) atomicAdd(&c[et[i]], 1);
    __syncthreads();
    if (threadIdx.x < TT && c[threadIdx.x] > 0)
        atomicAdd(&g_cnt[threadIdx.x], c[threadIdx.x]);
}

__global__ void k_scan() {
    int off = 0, tb = 0;
    for (int t = 0; t < TT; t++) {
        g_off[t] = off;
        g_cur[t] = off;
        g_tileBase[t] = tb;
        tb += (g_cnt[t] + TILE_E - 1) / TILE_E;
        off += g_cnt[t];
    }
    g_off[TT] = off;
    g_tileBase[TT] = tb;
}

__global__ void k_scatter(const int* __restrict__ et, int E) {
    __shared__ int c[TT], base[TT];
    if (threadIdx.x < TT) c[threadIdx.x] = 0;
    __syncthreads();
    int i = blockIdx.x * blockDim.x + threadIdx.x;
    int t = 0, pos = 0;
    bool valid = (i < E);
    if (valid) {
        t = et[i];
        pos = atomicAdd(&c[t], 1);
    }
    __syncthreads();
    if (threadIdx.x < TT)
        base[threadIdx.x] = (c[threadIdx.x] > 0)
            ? atomicAdd(&g_cur[threadIdx.x], c[threadIdx.x]) : 0;
    __syncthreads();
    if (valid) g_bucket[base[t] + pos] = i;
}

// ---------------- edge MLP + scatter-add ----------------
// CTA = 64 edges of one type. 256 threads; thread = 8 edges x 4 cols.
__global__ __launch_bounds__(256)
void k_mlp(const float* __restrict__ h,
           const int*   __restrict__ ei,     // [2,E]
           const float* __restrict__ ea,     // [E,A]
           const float* __restrict__ W1,     // [T,144,128]
           const float* __restrict__ b1,     // [T,128]
           const float* __restrict__ W2,     // [T,128,128]
           const float* __restrict__ b2,     // [T,128]
           int E) {
    __shared__ __align__(16) float s_x[HA * XS_STRIDE];   // x tile, later hidden tile
    __shared__ __align__(16) float ws[16 * HH];           // weight k-tile
    __shared__ int s_dst[TILE_E];
    __shared__ int s_src[TILE_E];
    __shared__ int s_eid[TILE_E];

    // which type / segment does this block own?
    int tb0 = g_tileBase[0], tb1 = g_tileBase[1], tb2 = g_tileBase[2],
        tb3 = g_tileBase[3], tb4 = g_tileBase[4];
    int b = blockIdx.x;
    if (b >= tb4) return;
    int t;
    if      (b < tb1) t = 0;
    else if (b < tb2) t = 1;
    else if (b < tb3) t = 2;
    else              t = 3;
    int tbt = (t == 0) ? tb0 : (t == 1) ? tb1 : (t == 2) ? tb2 : tb3;
    int localTile = b - tbt;
    int segBase = g_off[t] + localTile * TILE_E;
    int segCnt  = g_off[t + 1] - segBase;
    if (segCnt > TILE_E) segCnt = TILE_E;
    if (segCnt <= 0) return;

    const int* srcp = ei;
    const int* dstp = ei + E;

    // load edge metadata
    for (int i = threadIdx.x; i < TILE_E; i += 256) {
        if (i < segCnt) {
            int e = g_bucket[segBase + i];
            s_eid[i] = e;
            s_src[i] = srcp[e];
            s_dst[i] = dstp[e];
        } else {
            s_eid[i] = 0; s_src[i] = 0; s_dst[i] = -1;
        }
    }
    __syncthreads();

    // gather x transposed: s_x[j][i], warp-per-edge, conflict-free stride 65
    {
        int warp = threadIdx.x >> 5, lane = threadIdx.x & 31;
        for (int i = warp; i < TILE_E; i += 8) {
            int sidx = s_src[i];
            int e = s_eid[i];
            bool valid = (i < segCnt);
            for (int j = lane; j < HA; j += 32) {
                float v = 0.f;
                if (valid)
                    v = (j < HH) ? h[sidx * HH + j] : ea[e * AA + (j - HH)];
                s_x[j * XS_STRIDE + i] = v;
            }
        }
    }

    int tx = threadIdx.x & 31;   // 4 cols:  tx*4 .. tx*4+3
    int ty = threadIdx.x >> 5;   // 8 edges: ty*8 .. ty*8+7

    float acc[8][4];
    #pragma unroll
    for (int r = 0; r < 8; r++)
        #pragma unroll
        for (int c = 0; c < 4; c++) acc[r][c] = 0.f;

    // ---- GEMM1: hidden = relu(X @ W1[t] + b1[t]),  K = 144 ----
    const float* W1t = W1 + t * HA * HH;
    for (int k0 = 0; k0 < HA; k0 += 16) {
        __syncthreads();
        for (int i = threadIdx.x; i < 16 * HH; i += 256)
            ws[i] = W1t[k0 * HH + i];
        __syncthreads();
        #pragma unroll
        for (int kk = 0; kk < 16; kk++) {
            const float* xrow = &s_x[(k0 + kk) * XS_STRIDE + ty * 8];
            float4 w = *(const float4*)&ws[kk * HH + tx * 4];
            #pragma unroll
            for (int r = 0; r < 8; r++) {
                float xv = xrow[r];
                acc[r][0] += xv * w.x;
                acc[r][1] += xv * w.y;
                acc[r][2] += xv * w.z;
                acc[r][3] += xv * w.w;
            }
        }
    }

    // epilogue 1: relu + bias, store hidden transposed into s_x (x is dead)
    float4 b1v = *(const float4*)&b1[t * HH + tx * 4];
    __syncthreads();
    #pragma unroll
    for (int r = 0; r < 8; r++) {
        s_x[(tx * 4 + 0) * XS_STRIDE + ty * 8 + r] = fmaxf(acc[r][0] + b1v.x, 0.f);
        s_x[(tx * 4 + 1) * XS_STRIDE + ty * 8 + r] = fmaxf(acc[r][1] + b1v.y, 0.f);
        s_x[(tx * 4 + 2) * XS_STRIDE + ty * 8 + r] = fmaxf(acc[r][2] + b1v.z, 0.f);
        s_x[(tx * 4 + 3) * XS_STRIDE + ty * 8 + r] = fmaxf(acc[r][3] + b1v.w, 0.f);
    }
    __syncthreads();

    #pragma unroll
    for (int r = 0; r < 8; r++)
        #pragma unroll
        for (int c = 0; c < 4; c++) acc[r][c] = 0.f;

    // ---- GEMM2: m = hidden @ W2[t] + b2[t],  K = 128 ----
    const float* W2t = W2 + t * HH * HH;
    for (int k0 = 0; k0 < HH; k0 += 16) {
        __syncthreads();
        for (int i = threadIdx.x; i < 16 * HH; i += 256)
            ws[i] = W2t[k0 * HH + i];
        __syncthreads();
        #pragma unroll
        for (int kk = 0; kk < 16; kk++) {
            const float* xrow = &s_x[(k0 + kk) * XS_STRIDE + ty * 8];
            float4 w = *(const float4*)&ws[kk * HH + tx * 4];
            #pragma unroll
            for (int r = 0; r < 8; r++) {
                float xv = xrow[r];
                acc[r][0] += xv * w.x;
                acc[r][1] += xv * w.y;
                acc[r][2] += xv * w.z;
                acc[r][3] += xv * w.w;
            }
        }
    }

    // epilogue 2: bias + scatter-add to g_msg
    float4 b2v = *(const float4*)&b2[t * HH + tx * 4];
    #pragma unroll
    for (int r = 0; r < 8; r++) {
        int d = s_dst[ty * 8 + r];
        if (d >= 0) {
            float* mp = &g_msg[d * HH + tx * 4];
            atomicAdd(mp + 0, acc[r][0] + b2v.x);
            atomicAdd(mp + 1, acc[r][1] + b2v.y);
            atomicAdd(mp + 2, acc[r][2] + b2v.z);
            atomicAdd(mp + 3, acc[r][3] + b2v.w);
        }
    }
}

// ---------------- fused GRU cell ----------------
// CTA = 16 nodes, 256 threads; thread = 2 nodes x 4 j-cols x 4 planes (r,z,i_n,h_n)
__global__ __launch_bounds__(256)
void k_gru(const float* __restrict__ h,
           const float* __restrict__ b_ih,
           const float* __restrict__ b_hh,
           float* __restrict__ out, int N) {
    __shared__ __align__(16) float s_ms[HH * 16];
    __shared__ __align__(16) float s_h [HH * 16];
    __shared__ __align__(16) float s_wi[8 * 3 * HH];
    __shared__ __align__(16) float s_wh[8 * 3 * HH];
    __shared__ float s_bih[3 * HH];
    __shared__ float s_bhh[3 * HH];

    int n0 = blockIdx.x * 16;
    for (int i = threadIdx.x; i < 3 * HH; i += 256) {
        s_bih[i] = b_ih[i];
        s_bhh[i] = b_hh[i];
    }
    for (int idx = threadIdx.x; idx < 16 * HH; idx += 256) {
        int i = idx / HH, k = idx % HH;
        int n = n0 + i;
        float mv = 0.f, hv = 0.f;
        if (n < N) { mv = g_msg[n * HH + k]; hv = h[n * HH + k]; }
        s_ms[k * 16 + i] = mv;
        s_h [k * 16 + i] = hv;
    }

    int tx = threadIdx.x & 31;   // j = tx*4
    int ty = threadIdx.x >> 5;   // nodes ty*2, ty*2+1
    int j = tx * 4;
    int nb = ty * 2;

    float sr[2][4], sz[2][4], si[2][4], sh[2][4];
    #pragma unroll
    for (int i = 0; i < 2; i++)
        #pragma unroll
        for (int c = 0; c < 4; c++) { sr[i][c] = 0.f; sz[i][c] = 0.f; si[i][c] = 0.f; sh[i][c] = 0.f; }

    for (int k0 = 0; k0 < HH; k0 += 8) {
        __syncthreads();
        for (int idx = threadIdx.x; idx < 8 * 3 * HH; idx += 256) {
            s_wi[idx] = g_wihT[k0 * 3 * HH + idx];
            s_wh[idx] = g_whhT[k0 * 3 * HH + idx];
        }
        __syncthreads();
        #pragma unroll
        for (int kk = 0; kk < 8; kk++) {
            float m0 = s_ms[(k0 + kk) * 16 + nb];
            float m1 = s_ms[(k0 + kk) * 16 + nb + 1];
            float h0 = s_h [(k0 + kk) * 16 + nb];
            float h1 = s_h [(k0 + kk) * 16 + nb + 1];
            float wir[4], wiz[4], win[4], whr[4], whz[4], whn[4];
            {
                float4 a = *(const float4*)&s_wi[kk * 3 * HH + j];
                float4 bq = *(const float4*)&s_wi[kk * 3 * HH + 128 + j];
                float4 cq = *(const float4*)&s_wi[kk * 3 * HH + 256 + j];
                wir[0]=a.x; wir[1]=a.y; wir[2]=a.z; wir[3]=a.w;
                wiz[0]=bq.x; wiz[1]=bq.y; wiz[2]=bq.z; wiz[3]=bq.w;
                win[0]=cq.x; win[1]=cq.y; win[2]=cq.z; win[3]=cq.w;
                float4 d = *(const float4*)&s_wh[kk * 3 * HH + j];
                float4 e = *(const float4*)&s_wh[kk * 3 * HH + 128 + j];
                float4 f = *(const float4*)&s_wh[kk * 3 * HH + 256 + j];
                whr[0]=d.x; whr[1]=d.y; whr[2]=d.z; whr[3]=d.w;
                whz[0]=e.x; whz[1]=e.y; whz[2]=e.z; whz[3]=e.w;
                whn[0]=f.x; whn[1]=f.y; whn[2]=f.z; whn[3]=f.w;
            }
            #pragma unroll
            for (int c = 0; c < 4; c++) {
                sr[0][c] += m0 * wir[c] + h0 * whr[c];
                sr[1][c] += m1 * wir[c] + h1 * whr[c];
                sz[0][c] += m0 * wiz[c] + h0 * whz[c];
                sz[1][c] += m1 * wiz[c] + h1 * whz[c];
                si[0][c] += m0 * win[c];
                si[1][c] += m1 * win[c];
                sh[0][c] += h0 * whn[c];
                sh[1][c] += h1 * whn[c];
            }
        }
    }

    #pragma unroll
    for (int i = 0; i < 2; i++) {
        int n = n0 + nb + i;
        if (n >= N) continue;
        float o[4];
        #pragma unroll
        for (int c = 0; c < 4; c++) {
            int jc = j + c;
            float rg = sr[i][c] + s_bih[jc] + s_bhh[jc];
            rg = 1.f / (1.f + __expf(-rg));
            float zg = sz[i][c] + s_bih[128 + jc] + s_bhh[128 + jc];
            zg = 1.f / (1.f + __expf(-zg));
            float ing = si[i][c] + s_bih[256 + jc];
            float hng = sh[i][c] + s_bhh[256 + jc];
            float ng = tanhf(ing + rg * hng);
            float hv = s_h[jc * 16 + nb + i];
            o[c] = (1.f - zg) * ng + zg * hv;
        }
        *(float4*)&out[n * HH + j] = make_float4(o[0], o[1], o[2], o[3]);
    }
}

// ---------------- launch ----------------
extern "C" void kernel_launch(void* const* d_in, const int* in_sizes, int n_in,
                              void* d_out, int out_size) {
    const float* h    = (const float*)d_in[0];
    const int*   ei   = (const int*)  d_in[1];
    const int*   et   = (const int*)  d_in[2];
    const float* ea   = (const float*)d_in[3];
    const float* W1   = (const float*)d_in[4];
    const float* b1   = (const float*)d_in[5];
    const float* W2   = (const float*)d_in[6];
    const float* b2   = (const float*)d_in[7];
    const float* wih  = (const float*)d_in[8];
    const float* whh  = (const float*)d_in[9];
    const float* bih  = (const float*)d_in[10];
    const float* bhh  = (const float*)d_in[11];
    float* out = (float*)d_out;

    int N = in_sizes[0] / HH;   // 50000
    int E = in_sizes[2];        // 800000

    k_zero<<<2048, 256>>>();
    k_transpose<<<(HH * 3 * HH + 255) / 256, 256>>>(wih, whh);
    k_hist<<<(E + 255) / 256, 256>>>(et, E);
    k_scan<<<1, 1>>>();
    k_scatter<<<(E + 255) / 256, 256>>>(et, E);

    int mlpGrid = (E + TILE_E - 1) / TILE_E + TT;
    k_mlp<<<mlpGrid, 256>>>(h, ei, ea, W1, b1, W2, b2, E);

    k_gru<<<(N + 15) / 16, 256>>>(h, bih, bhh, out, N);
}

// round 4
// speedup vs baseline: 1.3723x; 1.3723x over previous
#include <cuda_runtime.h>

// Problem constants (fixed-shape problem)
#define NN 50000
#define HH 128
#define EE 800000
#define AA 16
#define TT 4
#define HA 144            // H + A
#define TILE_E 128
#define ES 130            // padded (even) edge-dim stride for x/hidden tiles
#define GNS 32            // GRU nodes per CTA
#define GS 33             // padded node stride for GRU staging

typedef unsigned long long u64;

// ---------------- f32x2 packed-math helpers ----------------
__device__ __forceinline__ u64 f2_pack(float lo, float hi) {
    u64 r;
    asm("mov.b64 %0, {%1,%2};" : "=l"(r)
        : "r"(__float_as_uint(lo)), "r"(__float_as_uint(hi)));
    return r;
}
__device__ __forceinline__ u64 f2_dup(float v) { return f2_pack(v, v); }
__device__ __forceinline__ void f2_fma(u64& d, u64 a, u64 b) {
    asm("fma.rn.f32x2 %0, %1, %2, %0;" : "+l"(d) : "l"(a), "l"(b));
}
__device__ __forceinline__ void f2_unpack(u64 v, float& lo, float& hi) {
    unsigned int l, h;
    asm("mov.b64 {%0,%1}, %2;" : "=r"(l), "=r"(h) : "l"(v));
    lo = __uint_as_float(l); hi = __uint_as_float(h);
}

// ---------------- device scratch (no allocations allowed) ----------------
__device__ float g_msg[NN * HH];          // scatter-add target [N,H]
__device__ int   g_bucket[EE];            // edge ids sorted by type
__device__ int   g_cnt[TT];
__device__ int   g_cur[TT];
__device__ int   g_off[TT + 1];
__device__ int   g_tileBase[TT + 1];
__device__ float g_wihT[HH * 3 * HH];     // w_ih transposed to [k][gate*H+col]
__device__ float g_whhT[HH * 3 * HH];

// ---------------- utility kernels ----------------
__global__ void k_zero() {
    int idx = blockIdx.x * blockDim.x + threadIdx.x;
    int stride = gridDim.x * blockDim.x;
    float4* p = reinterpret_cast<float4*>(g_msg);
    int total4 = NN * HH / 4;
    float4 z = make_float4(0.f, 0.f, 0.f, 0.f);
    for (int i = idx; i < total4; i += stride) p[i] = z;
    if (idx < TT) g_cnt[idx] = 0;
}

__global__ void k_transpose(const float* __restrict__ wih,
                            const float* __restrict__ whh) {
    int idx = blockIdx.x * blockDim.x + threadIdx.x;
    if (idx < HH * 3 * HH) {
        int k = idx / (3 * HH);
        int g = idx % (3 * HH);
        g_wihT[idx] = wih[g * HH + k];
        g_whhT[idx] = whh[g * HH + k];
    }
}

__global__ void k_hist(const int* __restrict__ et, int E) {
    __shared__ int c[TT];
    if (threadIdx.x < TT) c[threadIdx.x] = 0;
    __syncthreads();
    int i = blockIdx.x * blockDim.x + threadIdx.x;
    if (i < E) atomicAdd(&c[et[i]], 1);
    __syncthreads();
    if (threadIdx.x < TT && c[threadIdx.x] > 0)
        atomicAdd(&g_cnt[threadIdx.x], c[threadIdx.x]);
}

__global__ void k_scan() {
    int off = 0, tb = 0;
    for (int t = 0; t < TT; t++) {
        g_off[t] = off;
        g_cur[t] = off;
        g_tileBase[t] = tb;
        tb += (g_cnt[t] + TILE_E - 1) / TILE_E;
        off += g_cnt[t];
    }
    g_off[TT] = off;
    g_tileBase[TT] = tb;
}

__global__ void k_scatter(const int* __restrict__ et, int E) {
    __shared__ int c[TT], base[TT];
    if (threadIdx.x < TT) c[threadIdx.x] = 0;
    __syncthreads();
    int i = blockIdx.x * blockDim.x + threadIdx.x;
    int t = 0, pos = 0;
    bool valid = (i < E);
    if (valid) {
        t = et[i];
        pos = atomicAdd(&c[t], 1);
    }
    __syncthreads();
    if (threadIdx.x < TT)
        base[threadIdx.x] = (c[threadIdx.x] > 0)
            ? atomicAdd(&g_cur[threadIdx.x], c[threadIdx.x]) : 0;
    __syncthreads();
    if (valid) g_bucket[base[t] + pos] = i;
}

// ---------------- edge MLP + scatter-add ----------------
// CTA = 128 edges of one type; 256 threads.
// Thread = 8 edge-PAIRS (packed f32x2) x 4 cols (strided tx + 32c).
// Dynamic smem: sx[144*130] (x tile, later hidden tile) + ws[2][16*128].
__global__ __launch_bounds__(256, 2)
void k_mlp(const float* __restrict__ h,
           const int*   __restrict__ ei,     // [2,E]
           const float* __restrict__ ea,     // [E,A]
           const float* __restrict__ W1,     // [T,144,128]
           const float* __restrict__ b1,     // [T,128]
           const float* __restrict__ W2,     // [T,128,128]
           const float* __restrict__ b2,     // [T,128]
           int E) {
    extern __shared__ __align__(16) float dyn[];
    float* sx = dyn;                   // 144*130 = 18720 floats
    float* ws = dyn + HA * ES;         // 2 * 2048 floats

    __shared__ int s_dst[TILE_E];
    __shared__ int s_src[TILE_E];
    __shared__ int s_eid[TILE_E];

    int tid = threadIdx.x;

    // which type / segment does this block own?
    int tb1 = g_tileBase[1], tb2 = g_tileBase[2],
        tb3 = g_tileBase[3], tb4 = g_tileBase[4];
    int b = blockIdx.x;
    if (b >= tb4) return;
    int t;
    if      (b < tb1) t = 0;
    else if (b < tb2) t = 1;
    else if (b < tb3) t = 2;
    else              t = 3;
    int tbt = (t == 0) ? 0 : (t == 1) ? tb1 : (t == 2) ? tb2 : tb3;
    int segBase = g_off[t] + (b - tbt) * TILE_E;
    int segCnt  = g_off[t + 1] - segBase;
    if (segCnt > TILE_E) segCnt = TILE_E;
    if (segCnt <= 0) return;

    const int* srcp = ei;
    const int* dstp = ei + E;

    // load edge metadata
    for (int i = tid; i < TILE_E; i += 256) {
        if (i < segCnt) {
            int e = g_bucket[segBase + i];
            s_eid[i] = e;
            s_src[i] = srcp[e];
            s_dst[i] = dstp[e];
        } else {
            s_eid[i] = 0; s_src[i] = 0; s_dst[i] = -1;
        }
    }
    __syncthreads();

    // gather x transposed: sx[j][i], warp-per-edge
    {
        int warp = tid >> 5, lane = tid & 31;
        for (int i = warp; i < TILE_E; i += 8) {
            int sidx = s_src[i];
            int e = s_eid[i];
            bool valid = (i < segCnt);
            for (int j = lane; j < HA; j += 32) {
                float v = 0.f;
                if (valid)
                    v = (j < HH) ? h[sidx * HH + j] : ea[e * AA + (j - HH)];
                sx[j * ES + i] = v;
            }
        }
    }

    int tx = tid & 31;   // cols: tx + 32*c
    int ty = tid >> 5;   // edges: ty*16 .. ty*16+15 (8 pairs)

    u64 acc[8][4];
    #pragma unroll
    for (int p = 0; p < 8; p++)
        #pragma unroll
        for (int c = 0; c < 4; c++) acc[p][c] = 0ull;

    float4 st0, st1;  // weight staging

    // ---- GEMM1: hidden = relu(X @ W1[t] + b1[t]),  K = 144, 9 k-tiles ----
    const float* W1t = W1 + t * HA * HH;
    {
        const float4* g4 = (const float4*)W1t;
        st0 = g4[tid * 2]; st1 = g4[tid * 2 + 1];
        float4* s4 = (float4*)ws;
        s4[tid * 2] = st0; s4[tid * 2 + 1] = st1;
    }
    __syncthreads();

    for (int kt = 0; kt < 9; kt++) {
        int buf = kt & 1;
        if (kt + 1 < 9) {
            const float4* g4 = (const float4*)(W1t + (kt + 1) * 16 * HH);
            st0 = g4[tid * 2]; st1 = g4[tid * 2 + 1];
        }
        const float* wsb = ws + buf * (16 * HH);
        int k0 = kt * 16;
        #pragma unroll
        for (int kk = 0; kk < 16; kk++) {
            const float* xr = &sx[(k0 + kk) * ES + ty * 16];
            u64 xp[8];
            #pragma unroll
            for (int p = 0; p < 8; p++)
                xp[p] = *(const u64*)&xr[2 * p];
            const float* wr = &wsb[kk * HH + tx];
            u64 wd0 = f2_dup(wr[0]);
            u64 wd1 = f2_dup(wr[32]);
            u64 wd2 = f2_dup(wr[64]);
            u64 wd3 = f2_dup(wr[96]);
            #pragma unroll
            for (int p = 0; p < 8; p++) {
                f2_fma(acc[p][0], xp[p], wd0);
                f2_fma(acc[p][1], xp[p], wd1);
                f2_fma(acc[p][2], xp[p], wd2);
                f2_fma(acc[p][3], xp[p], wd3);
            }
        }
        if (kt + 1 < 9) {
            float4* s4 = (float4*)(ws + (buf ^ 1) * (16 * HH));
            s4[tid * 2] = st0; s4[tid * 2 + 1] = st1;
        }
        __syncthreads();
    }

    // epilogue 1: relu + bias, store hidden transposed back into sx (x dead)
    {
        float bq[4];
        #pragma unroll
        for (int c = 0; c < 4; c++) bq[c] = b1[t * HH + tx + 32 * c];
        // all GEMM1 reads of sx completed (sync at loop end)
        #pragma unroll
        for (int p = 0; p < 8; p++) {
            #pragma unroll
            for (int c = 0; c < 4; c++) {
                float lo, hi;
                f2_unpack(acc[p][c], lo, hi);
                lo = fmaxf(lo + bq[c], 0.f);
                hi = fmaxf(hi + bq[c], 0.f);
                *(u64*)&sx[(tx + 32 * c) * ES + ty * 16 + 2 * p] = f2_pack(lo, hi);
                acc[p][c] = 0ull;
            }
        }
    }
    __syncthreads();

    // ---- GEMM2: m = hidden @ W2[t] + b2[t],  K = 128, 8 k-tiles ----
    const float* W2t = W2 + t * HH * HH;
    {
        const float4* g4 = (const float4*)W2t;
        st0 = g4[tid * 2]; st1 = g4[tid * 2 + 1];
        float4* s4 = (float4*)ws;
        s4[tid * 2] = st0; s4[tid * 2 + 1] = st1;
    }
    __syncthreads();

    for (int kt = 0; kt < 8; kt++) {
        int buf = kt & 1;
        if (kt + 1 < 8) {
            const float4* g4 = (const float4*)(W2t + (kt + 1) * 16 * HH);
            st0 = g4[tid * 2]; st1 = g4[tid * 2 + 1];
        }
        const float* wsb = ws + buf * (16 * HH);
        int k0 = kt * 16;
        #pragma unroll
        for (int kk = 0; kk < 16; kk++) {
            const float* xr = &sx[(k0 + kk) * ES + ty * 16];
            u64 xp[8];
            #pragma unroll
            for (int p = 0; p < 8; p++)
                xp[p] = *(const u64*)&xr[2 * p];
            const float* wr = &wsb[kk * HH + tx];
            u64 wd0 = f2_dup(wr[0]);
            u64 wd1 = f2_dup(wr[32]);
            u64 wd2 = f2_dup(wr[64]);
            u64 wd3 = f2_dup(wr[96]);
            #pragma unroll
            for (int p = 0; p < 8; p++) {
                f2_fma(acc[p][0], xp[p], wd0);
                f2_fma(acc[p][1], xp[p], wd1);
                f2_fma(acc[p][2], xp[p], wd2);
                f2_fma(acc[p][3], xp[p], wd3);
            }
        }
        if (kt + 1 < 8) {
            float4* s4 = (float4*)(ws + (buf ^ 1) * (16 * HH));
            s4[tid * 2] = st0; s4[tid * 2 + 1] = st1;
        }
        __syncthreads();
    }

    // epilogue 2: bias + scatter-add to g_msg (lanes share edge -> coalesced)
    {
        float bq[4];
        #pragma unroll
        for (int c = 0; c < 4; c++) bq[c] = b2[t * HH + tx + 32 * c];
        #pragma unroll
        for (int p = 0; p < 8; p++) {
            int e0 = ty * 16 + 2 * p;
            int d0 = s_dst[e0];
            int d1 = s_dst[e0 + 1];
            #pragma unroll
            for (int c = 0; c < 4; c++) {
                float lo, hi;
                f2_unpack(acc[p][c], lo, hi);
                if (d0 >= 0) atomicAdd(&g_msg[d0 * HH + tx + 32 * c], lo + bq[c]);
                if (d1 >= 0) atomicAdd(&g_msg[d1 * HH + tx + 32 * c], hi + bq[c]);
            }
        }
    }
}

// ---------------- fused GRU cell ----------------
// CTA = 32 nodes, 256 threads; thread = 4 nodes x 4 cols (2 col-pairs, f32x2)
// Dynamic smem: s_ms[128*33] + s_h[128*33] + wi[2][8*384] + wh[2][8*384]
__global__ __launch_bounds__(256, 2)
void k_gru(const float* __restrict__ h,
           const float* __restrict__ b_ih,
           const float* __restrict__ b_hh,
           float* __restrict__ out, int N) {
    extern __shared__ __align__(16) float gdyn[];
    float* s_ms = gdyn;                        // 128*33 = 4224
    float* s_h  = gdyn + HH * GS;              // 4224
    float* s_wi = gdyn + 2 * HH * GS;          // 2 * 3072
    float* s_wh = s_wi + 2 * 8 * 3 * HH;       // 2 * 3072

    int tid = threadIdx.x;
    int n0 = blockIdx.x * GNS;

    for (int idx = tid; idx < GNS * HH; idx += 256) {
        int i = idx >> 7, k = idx & 127;
        int n = n0 + i;
        float mv = 0.f, hv = 0.f;
        if (n < N) { mv = g_msg[n * HH + k]; hv = h[n * HH + k]; }
        s_ms[k * GS + i] = mv;
        s_h [k * GS + i] = hv;
    }

    int tx = tid & 31;   // j = tx*4 (cols j..j+3 as 2 pairs)
    int ty = tid >> 5;   // nodes ty*4 .. ty*4+3
    int j = tx * 4;

    u64 ar[4][2], az[4][2], ai[4][2], ah[4][2];
    #pragma unroll
    for (int q = 0; q < 4; q++)
        #pragma unroll
        for (int cp = 0; cp < 2; cp++) {
            ar[q][cp] = 0ull; az[q][cp] = 0ull;
            ai[q][cp] = 0ull; ah[q][cp] = 0ull;
        }

    // weight staging: per tile 3072 floats per array -> 3 float4 per thread
    float4 wi0, wi1, wi2, wh0, wh1, wh2;
    {
        const float4* gi = (const float4*)g_wihT;
        const float4* gh = (const float4*)g_whhT;
        wi0 = gi[tid * 3]; wi1 = gi[tid * 3 + 1]; wi2 = gi[tid * 3 + 2];
        wh0 = gh[tid * 3]; wh1 = gh[tid * 3 + 1]; wh2 = gh[tid * 3 + 2];
        float4* si = (float4*)s_wi;
        float4* sh = (float4*)s_wh;
        si[tid * 3] = wi0; si[tid * 3 + 1] = wi1; si[tid * 3 + 2] = wi2;
        sh[tid * 3] = wh0; sh[tid * 3 + 1] = wh1; sh[tid * 3 + 2] = wh2;
    }
    __syncthreads();

    for (int kt = 0; kt < 16; kt++) {
        int buf = kt & 1;
        if (kt + 1 < 16) {
            const float4* gi = (const float4*)(g_wihT + (kt + 1) * 8 * 3 * HH);
            const float4* gh = (const float4*)(g_whhT + (kt + 1) * 8 * 3 * HH);
            wi0 = gi[tid * 3]; wi1 = gi[tid * 3 + 1]; wi2 = gi[tid * 3 + 2];
            wh0 = gh[tid * 3]; wh1 = gh[tid * 3 + 1]; wh2 = gh[tid * 3 + 2];
        }
        const float* wib = s_wi + buf * (8 * 3 * HH);
        const float* whb = s_wh + buf * (8 * 3 * HH);
        int k0 = kt * 8;
        #pragma unroll
        for (int kk = 0; kk < 8; kk++) {
            int k = k0 + kk;
            u64 md[4], hd[4];
            #pragma unroll
            for (int q = 0; q < 4; q++) {
                md[q] = f2_dup(s_ms[k * GS + ty * 4 + q]);
                hd[q] = f2_dup(s_h [k * GS + ty * 4 + q]);
            }
            const float* wr = &wib[kk * 3 * HH];
            const float* hr = &whb[kk * 3 * HH];
            ulonglong2 wir = *(const ulonglong2*)&wr[j];
            ulonglong2 wiz = *(const ulonglong2*)&wr[HH + j];
            ulonglong2 win = *(const ulonglong2*)&wr[2 * HH + j];
            ulonglong2 whr = *(const ulonglong2*)&hr[j];
            ulonglong2 whz = *(const ulonglong2*)&hr[HH + j];
            ulonglong2 whn = *(const ulonglong2*)&hr[2 * HH + j];
            #pragma unroll
            for (int q = 0; q < 4; q++) {
                f2_fma(ar[q][0], md[q], wir.x); f2_fma(ar[q][0], hd[q], whr.x);
                f2_fma(ar[q][1], md[q], wir.y); f2_fma(ar[q][1], hd[q], whr.y);
                f2_fma(az[q][0], md[q], wiz.x); f2_fma(az[q][0], hd[q], whz.x);
                f2_fma(az[q][1], md[q], wiz.y); f2_fma(az[q][1], hd[q], whz.y);
                f2_fma(ai[q][0], md[q], win.x);
                f2_fma(ai[q][1], md[q], win.y);
                f2_fma(ah[q][0], hd[q], whn.x);
                f2_fma(ah[q][1], hd[q], whn.y);
            }
        }
        if (kt + 1 < 16) {
            float4* si = (float4*)(s_wi + (buf ^ 1) * (8 * 3 * HH));
            float4* sh = (float4*)(s_wh + (buf ^ 1) * (8 * 3 * HH));
            si[tid * 3] = wi0; si[tid * 3 + 1] = wi1; si[tid * 3 + 2] = wi2;
            sh[tid * 3] = wh0; sh[tid * 3 + 1] = wh1; sh[tid * 3 + 2] = wh2;
        }
        __syncthreads();
    }

    // epilogue: gates + blend, write out
    #pragma unroll
    for (int q = 0; q < 4; q++) {
        int i = ty * 4 + q;
        int n = n0 + i;
        if (n >= N) continue;
        float sr[4], sz[4], si4[4], sh4[4];
        f2_unpack(ar[q][0], sr[0], sr[1]);  f2_unpack(ar[q][1], sr[2], sr[3]);
        f2_unpack(az[q][0], sz[0], sz[1]);  f2_unpack(az[q][1], sz[2], sz[3]);
        f2_unpack(ai[q][0], si4[0], si4[1]); f2_unpack(ai[q][1], si4[2], si4[3]);
        f2_unpack(ah[q][0], sh4[0], sh4[1]); f2_unpack(ah[q][1], sh4[2], sh4[3]);
        float o[4];
        #pragma unroll
        for (int c = 0; c < 4; c++) {
            int jc = j + c;
            float rg = sr[c] + b_ih[jc] + b_hh[jc];
            rg = 1.f / (1.f + __expf(-rg));
            float zg = sz[c] + b_ih[HH + jc] + b_hh[HH + jc];
            zg = 1.f / (1.f + __expf(-zg));
            float ing = si4[c] + b_ih[2 * HH + jc];
            float hng = sh4[c] + b_hh[2 * HH + jc];
            float ng = tanhf(ing + rg * hng);
            float hv = s_h[jc * GS + i];
            o[c] = (1.f - zg) * ng + zg * hv;
        }
        *(float4*)&out[n * HH + j] = make_float4(o[0], o[1], o[2], o[3]);
    }
}

// ---------------- launch ----------------
extern "C" void kernel_launch(void* const* d_in, const int* in_sizes, int n_in,
                              void* d_out, int out_size) {
    const float* h    = (const float*)d_in[0];
    const int*   ei   = (const int*)  d_in[1];
    const int*   et   = (const int*)  d_in[2];
    const float* ea   = (const float*)d_in[3];
    const float* W1   = (const float*)d_in[4];
    const float* b1   = (const float*)d_in[5];
    const float* W2   = (const float*)d_in[6];
    const float* b2   = (const float*)d_in[7];
    const float* wih  = (const float*)d_in[8];
    const float* whh  = (const float*)d_in[9];
    const float* bih  = (const float*)d_in[10];
    const float* bhh  = (const float*)d_in[11];
    float* out = (float*)d_out;

    int N = in_sizes[0] / HH;   // 50000
    int E = in_sizes[2];        // 800000

    // dynamic smem sizes
    const int mlpSmem = (HA * ES + 2 * 16 * HH) * (int)sizeof(float);       // 91264 B
    const int gruSmem = (2 * HH * GS + 4 * 8 * 3 * HH) * (int)sizeof(float); // 82944 B
    cudaFuncSetAttribute(k_mlp, cudaFuncAttributeMaxDynamicSharedMemorySize, mlpSmem);
    cudaFuncSetAttribute(k_gru, cudaFuncAttributeMaxDynamicSharedMemorySize, gruSmem);

    k_zero<<<2048, 256>>>();
    k_transpose<<<(HH * 3 * HH + 255) / 256, 256>>>(wih, whh);
    k_hist<<<(E + 255) / 256, 256>>>(et, E);
    k_scan<<<1, 1>>>();
    k_scatter<<<(E + 255) / 256, 256>>>(et, E);

    int mlpGrid = (E + TILE_E - 1) / TILE_E + TT;
    k_mlp<<<mlpGrid, 256, mlpSmem>>>(h, ei, ea, W1, b1, W2, b2, E);

    k_gru<<<(N + GNS - 1) / GNS, 256, gruSmem>>>(h, bih, bhh, out, N);
}

// round 7
// speedup vs baseline: 1.3929x; 1.0150x over previous
#include <cuda_runtime.h>
#include <cuda_bf16.h>
#include <cstdint>

// Problem constants (fixed-shape problem)
#define NN 50000
#define HH 128
#define EE 800000
#define AA 16
#define TT 4
#define HA 144            // H + A
#define TILE_E 128
#define KP 152            // bf16 K stride (pad: ldmatrix conflict-free)
#define SF 132            // float staging stride for epilogue2
#define GNS 32            // GRU nodes per CTA
#define GS 33             // padded node stride for GRU staging

typedef unsigned long long u64;

// ---------------- f32x2 packed-math helpers (GRU) ----------------
__device__ __forceinline__ u64 f2_pack(float lo, float hi) {
    u64 r;
    asm("mov.b64 %0, {%1,%2};" : "=l"(r)
        : "r"(__float_as_uint(lo)), "r"(__float_as_uint(hi)));
    return r;
}
__device__ __forceinline__ u64 f2_dup(float v) { return f2_pack(v, v); }
__device__ __forceinline__ void f2_fma(u64& d, u64 a, u64 b) {
    asm("fma.rn.f32x2 %0, %1, %2, %0;" : "+l"(d) : "l"(a), "l"(b));
}
__device__ __forceinline__ void f2_unpack(u64 v, float& lo, float& hi) {
    unsigned int l, h;
    asm("mov.b64 {%0,%1}, %2;" : "=r"(l), "=r"(h) : "l"(v));
    lo = __uint_as_float(l); hi = __uint_as_float(h);
}

// ---------------- mma.sync helpers ----------------
__device__ __forceinline__ uint32_t smem_u32(const void* p) {
    uint32_t a;
    asm("{ .reg .u64 t; cvta.to.shared.u64 t, %1; cvt.u32.u64 %0, t; }"
        : "=r"(a) : "l"(p));
    return a;
}
__device__ __forceinline__ void ldsm4(uint32_t& r0, uint32_t& r1,
                                      uint32_t& r2, uint32_t& r3, uint32_t addr) {
    asm volatile("ldmatrix.sync.aligned.m8n8.x4.shared.b16 {%0,%1,%2,%3}, [%4];"
                 : "=r"(r0), "=r"(r1), "=r"(r2), "=r"(r3) : "r"(addr));
}
__device__ __forceinline__ void mma16816(float* d, const uint32_t* a, const uint32_t* b) {
    asm volatile("mma.sync.aligned.m16n8k16.row.col.f32.bf16.bf16.f32 "
                 "{%0,%1,%2,%3},{%4,%5,%6,%7},{%8,%9},{%0,%1,%2,%3};"
                 : "+f"(d[0]), "+f"(d[1]), "+f"(d[2]), "+f"(d[3])
                 : "r"(a[0]), "r"(a[1]), "r"(a[2]), "r"(a[3]),
                   "r"(b[0]), "r"(b[1]));
}

// bf16 hi/lo split of a float
__device__ __forceinline__ void bf_split(float v, __nv_bfloat16& hi, __nv_bfloat16& lo) {
    hi = __float2bfloat16(v);
    lo = __float2bfloat16(v - __bfloat162float(hi));
}

// ---------------- device scratch ----------------
__device__ float g_msg[NN * HH];
__device__ int   g_bucket[EE];
__device__ int   g_cnt[TT];
__device__ int   g_cur[TT];
__device__ int   g_off[TT + 1];
__device__ int   g_tileBase[TT + 1];
__device__ float g_wihT[HH * 3 * HH];
__device__ float g_whhT[HH * 3 * HH];
// bf16 weight images, W^T [N=128][KP] row-major, hi/lo splits
__device__ __align__(16) __nv_bfloat16 g_W1b[TT][2][128 * KP];
__device__ __align__(16) __nv_bfloat16 g_W2b[TT][2][128 * KP];

// ---------------- utility kernels ----------------
__global__ void k_zero() {
    int idx = blockIdx.x * blockDim.x + threadIdx.x;
    int stride = gridDim.x * blockDim.x;
    float4* p = reinterpret_cast<float4*>(g_msg);
    int total4 = NN * HH / 4;
    float4 z = make_float4(0.f, 0.f, 0.f, 0.f);
    for (int i = idx; i < total4; i += stride) p[i] = z;
    if (idx < TT) g_cnt[idx] = 0;
}

__global__ void k_transpose(const float* __restrict__ wih,
                            const float* __restrict__ whh) {
    int idx = blockIdx.x * blockDim.x + threadIdx.x;
    if (idx < HH * 3 * HH) {
        int k = idx / (3 * HH);
        int g = idx % (3 * HH);
        g_wihT[idx] = wih[g * HH + k];
        g_whhT[idx] = whh[g * HH + k];
    }
}

// Build bf16 hi/lo images of W1^T, W2^T as [n][k] row-major with KP stride.
__global__ void k_prepW(const float* __restrict__ W1, const float* __restrict__ W2) {
    int idx = blockIdx.x * blockDim.x + threadIdx.x;
    const int per = 128 * KP;
    if (idx < TT * per) {
        int t = idx / per;
        int rem = idx % per;
        int n = rem / KP, k = rem % KP;
        float v = (k < HA) ? W1[(t * HA + k) * HH + n] : 0.f;
        __nv_bfloat16 hi, lo; bf_split(v, hi, lo);
        g_W1b[t][0][n * KP + k] = hi;
        g_W1b[t][1][n * KP + k] = lo;
    } else if (idx < 2 * TT * per) {
        int j = idx - TT * per;
        int t = j / per;
        int rem = j % per;
        int n = rem / KP, k = rem % KP;
        float v = (k < HH) ? W2[(t * HH + k) * HH + n] : 0.f;
        __nv_bfloat16 hi, lo; bf_split(v, hi, lo);
        g_W2b[t][0][n * KP + k] = hi;
        g_W2b[t][1][n * KP + k] = lo;
    }
}

__global__ void k_hist(const int* __restrict__ et, int E) {
    __shared__ int c[TT];
    if (threadIdx.x < TT) c[threadIdx.x] = 0;
    __syncthreads();
    int i = blockIdx.x * blockDim.x + threadIdx.x;
    if (i < E) atomicAdd(&c[et[i]], 1);
    __syncthreads();
    if (threadIdx.x < TT && c[threadIdx.x] > 0)
        atomicAdd(&g_cnt[threadIdx.x], c[threadIdx.x]);
}

__global__ void k_scan() {
    int off = 0, tb = 0;
    for (int t = 0; t < TT; t++) {
        g_off[t] = off;
        g_cur[t] = off;
        g_tileBase[t] = tb;
        tb += (g_cnt[t] + TILE_E - 1) / TILE_E;
        off += g_cnt[t];
    }
    g_off[TT] = off;
    g_tileBase[TT] = tb;
}

__global__ void k_scatter(const int* __restrict__ et, int E) {
    __shared__ int c[TT], base[TT];
    if (threadIdx.x < TT) c[threadIdx.x] = 0;
    __syncthreads();
    int i = blockIdx.x * blockDim.x + threadIdx.x;
    int t = 0, pos = 0;
    bool valid = (i < E);
    if (valid) {
        t = et[i];
        pos = atomicAdd(&c[t], 1);
    }
    __syncthreads();
    if (threadIdx.x < TT)
        base[threadIdx.x] = (c[threadIdx.x] > 0)
            ? atomicAdd(&g_cur[threadIdx.x], c[threadIdx.x]) : 0;
    __syncthreads();
    if (valid) g_bucket[base[t] + pos] = i;
}

// ---------------- bf16-split warp GEMM core ----------------
// Warp computes D[32 x 64] at (m0, n0). A,B in smem, row-major [128][KP] bf16,
// plain ldmatrix for both A-frags and B-frags (B stored [n][k], k contiguous).
template <int KSTEPS>
__device__ __forceinline__ void gemm_split(uint32_t aHi, uint32_t aLo,
                                           uint32_t bHi, uint32_t bLo,
                                           int lane, int m0, int n0,
                                           float d[2][8][4]) {
    uint32_t aRow = (uint32_t)(lane & 15);
    uint32_t aK   = (uint32_t)((lane >> 4) << 3);
    uint32_t bRow = (uint32_t)((lane & 7) + ((lane >> 4) << 3));
    uint32_t bK   = (uint32_t)(((lane >> 3) & 1) << 3);
    uint32_t aOff0 = ((uint32_t)(m0 + aRow) * KP + aK) * 2;
    uint32_t aOff1 = aOff0 + 16 * KP * 2;
    uint32_t bOff[4];
    #pragma unroll
    for (int j = 0; j < 4; j++)
        bOff[j] = ((uint32_t)(n0 + j * 16 + bRow) * KP + bK) * 2;

    #pragma unroll 1
    for (int ks = 0; ks < KSTEPS; ks++) {
        uint32_t kb = (uint32_t)ks * 32;   // 16 bf16 = 32 bytes
        uint32_t ah[2][4], al[2][4];
        ldsm4(ah[0][0], ah[0][1], ah[0][2], ah[0][3], aHi + aOff0 + kb);
        ldsm4(ah[1][0], ah[1][1], ah[1][2], ah[1][3], aHi + aOff1 + kb);
        ldsm4(al[0][0], al[0][1], al[0][2], al[0][3], aLo + aOff0 + kb);
        ldsm4(al[1][0], al[1][1], al[1][2], al[1][3], aLo + aOff1 + kb);
        uint32_t bh[8][2], bl[8][2];
        #pragma unroll
        for (int j = 0; j < 4; j++) {
            uint32_t r0, r1, r2, r3;
            ldsm4(r0, r1, r2, r3, bHi + bOff[j] + kb);
            bh[2 * j][0] = r0; bh[2 * j][1] = r1;
            bh[2 * j + 1][0] = r2; bh[2 * j + 1][1] = r3;
            ldsm4(r0, r1, r2, r3, bLo + bOff[j] + kb);
            bl[2 * j][0] = r0; bl[2 * j][1] = r1;
            bl[2 * j + 1][0] = r2; bl[2 * j + 1][1] = r3;
        }
        #pragma unroll
        for (int mt = 0; mt < 2; mt++)
            #pragma unroll
            for (int nt = 0; nt < 8; nt++) {
                mma16816(d[mt][nt], ah[mt], bh[nt]);
                mma16816(d[mt][nt], ah[mt], bl[nt]);
                mma16816(d[mt][nt], al[mt], bh[nt]);
            }
    }
}

// ---------------- edge MLP via mma.sync bf16 hi/lo split ----------------
// CTA = 128 edges of one type, 256 threads (8 warps: 4M x 2N).
// dyn smem: A_hi | A_lo | B_hi | B_lo, each 128*KP bf16 = 38912 B.
__global__ __launch_bounds__(256, 1)
void k_mlp(const float* __restrict__ h,
           const int*   __restrict__ ei,
           const float* __restrict__ ea,
           const float* __restrict__ b1,
           const float* __restrict__ b2,
           int E) {
    extern __shared__ __align__(16) char dsm[];
    __nv_bfloat16* sAhi = (__nv_bfloat16*)dsm;
    __nv_bfloat16* sAlo = sAhi + 128 * KP;
    __nv_bfloat16* sBhi = sAlo + 128 * KP;
    __nv_bfloat16* sBlo = sBhi + 128 * KP;
    float* stagef = (float*)dsm;       // epilogue2 staging (reuses A region)

    __shared__ int s_dst[TILE_E], s_src[TILE_E], s_eid[TILE_E];
    __shared__ float s_b1[HH], s_b2[HH];

    int tid = threadIdx.x;
    int wid = tid >> 5;
    int lane = tid & 31;

    // segment lookup
    int tb1 = g_tileBase[1], tb2 = g_tileBase[2],
        tb3 = g_tileBase[3], tb4 = g_tileBase[4];
    int b = blockIdx.x;
    if (b >= tb4) return;
    int t;
    if      (b < tb1) t = 0;
    else if (b < tb2) t = 1;
    else if (b < tb3) t = 2;
    else              t = 3;
    int tbt = (t == 0) ? 0 : (t == 1) ? tb1 : (t == 2) ? tb2 : tb3;
    int segBase = g_off[t] + (b - tbt) * TILE_E;
    int segCnt  = g_off[t + 1] - segBase;
    if (segCnt > TILE_E) segCnt = TILE_E;
    if (segCnt <= 0) return;

    const int* srcp = ei;
    const int* dstp = ei + E;
    for (int i = tid; i < TILE_E; i += 256) {
        if (i < segCnt) {
            int e = g_bucket[segBase + i];
            s_eid[i] = e; s_src[i] = srcp[e]; s_dst[i] = dstp[e];
        } else {
            s_eid[i] = 0; s_src[i] = 0; s_dst[i] = -1;
        }
        if (i < HH) { s_b1[i] = b1[t * HH + i]; s_b2[i] = b2[t * HH + i]; }
    }
    // copy W1 images into B buffers (bulk float4)
    {
        const float4* s0 = (const float4*)&g_W1b[t][0][0];
        const float4* s1 = (const float4*)&g_W1b[t][1][0];
        float4* d0 = (float4*)sBhi;
        float4* d1 = (float4*)sBlo;
        const int n4 = 128 * KP * 2 / 16;   // 2432
        for (int i = tid; i < n4; i += 256) { d0[i] = s0[i]; d1[i] = s1[i]; }
    }
    __syncthreads();

    // gather x -> bf16 hi/lo into A buffers (warp per edge row)
    for (int i = wid; i < TILE_E; i += 8) {
        bool valid = (i < segCnt);
        int sidx = s_src[i], e = s_eid[i];
        #pragma unroll
        for (int c = 0; c < 4; c++) {
            int j = lane + 32 * c;
            float v = valid ? h[sidx * HH + j] : 0.f;
            __nv_bfloat16 hi, lo; bf_split(v, hi, lo);
            sAhi[i * KP + j] = hi; sAlo[i * KP + j] = lo;
        }
        if (lane < AA) {
            int j = HH + lane;
            float v = valid ? ea[e * AA + lane] : 0.f;
            __nv_bfloat16 hi, lo; bf_split(v, hi, lo);
            sAhi[i * KP + j] = hi; sAlo[i * KP + j] = lo;
        }
    }
    __syncthreads();

    uint32_t aHi = smem_u32(sAhi), aLo = smem_u32(sAlo);
    uint32_t bHi = smem_u32(sBhi), bLo = smem_u32(sBlo);
    int m0 = (wid & 3) * 32;
    int n0 = (wid >> 2) * 64;

    float d[2][8][4];
    #pragma unroll
    for (int mt = 0; mt < 2; mt++)
        #pragma unroll
        for (int nt = 0; nt < 8; nt++)
            #pragma unroll
            for (int q = 0; q < 4; q++) d[mt][nt][q] = 0.f;

    // ---- GEMM1: K = 144 (9 k-steps) ----
    gemm_split<9>(aHi, aLo, bHi, bLo, lane, m0, n0, d);
    __syncthreads();   // everyone done reading A/B

    // epilogue 1: relu(d + b1) -> hi/lo bf16 back into A buffers as GEMM2 A
    {
        int rbase = m0 + (lane >> 2);
        int cbase = n0 + 2 * (lane & 3);
        #pragma unroll
        for (int mt = 0; mt < 2; mt++) {
            #pragma unroll
            for (int nt = 0; nt < 8; nt++) {
                int col = cbase + nt * 8;
                float bb0 = s_b1[col], bb1 = s_b1[col + 1];
                #pragma unroll
                for (int half = 0; half < 2; half++) {
                    int r = rbase + mt * 16 + half * 8;
                    float v0 = fmaxf(d[mt][nt][2 * half] + bb0, 0.f);
                    float v1 = fmaxf(d[mt][nt][2 * half + 1] + bb1, 0.f);
                    __nv_bfloat16 h0, l0, h1, l1;
                    bf_split(v0, h0, l0); bf_split(v1, h1, l1);
                    __nv_bfloat162 hp(h0, h1), lp(l0, l1);
                    *(uint32_t*)&sAhi[r * KP + col] = *(uint32_t*)&hp;
                    *(uint32_t*)&sAlo[r * KP + col] = *(uint32_t*)&lp;
                    d[mt][nt][2 * half] = 0.f;
                    d[mt][nt][2 * half + 1] = 0.f;
                }
            }
        }
    }
    // copy W2 images into B buffers
    {
        const float4* s0 = (const float4*)&g_W2b[t][0][0];
        const float4* s1 = (const float4*)&g_W2b[t][1][0];
        float4* d0 = (float4*)sBhi;
        float4* d1 = (float4*)sBlo;
        const int n4 = 128 * KP * 2 / 16;
        for (int i = tid; i < n4; i += 256) { d0[i] = s0[i]; d1[i] = s1[i]; }
    }
    __syncthreads();

    // ---- GEMM2: K = 128 (8 k-steps) ----
    gemm_split<8>(aHi, aLo, bHi, bLo, lane, m0, n0, d);
    __syncthreads();   // done reading A before staging overwrites it

    // epilogue 2: stage d + b2 as fp32 into stagef[edge][col]
    {
        int rbase = m0 + (lane >> 2);
        int cbase = n0 + 2 * (lane & 3);
        #pragma unroll
        for (int mt = 0; mt < 2; mt++) {
            #pragma unroll
            for (int nt = 0; nt < 8; nt++) {
                int col = cbase + nt * 8;
                float bb0 = s_b2[col], bb1 = s_b2[col + 1];
                #pragma unroll
                for (int half = 0; half < 2; half++) {
                    int r = rbase + mt * 16 + half * 8;
                    stagef[r * SF + col]     = d[mt][nt][2 * half] + bb0;
                    stagef[r * SF + col + 1] = d[mt][nt][2 * half + 1] + bb1;
                }
            }
        }
    }
    __syncthreads();

    // coalesced scatter-add flush (warp per edge row)
    for (int i = wid; i < TILE_E; i += 8) {
        int dstn = s_dst[i];
        if (dstn < 0) continue;
        #pragma unroll
        for (int c = 0; c < 4; c++) {
            int j = lane + 32 * c;
            atomicAdd(&g_msg[dstn * HH + j], stagef[i * SF + j]);
        }
    }
}

// ---------------- fused GRU cell (unchanged, f32x2) ----------------
__global__ __launch_bounds__(256, 2)
void k_gru(const float* __restrict__ h,
           const float* __restrict__ b_ih,
           const float* __restrict__ b_hh,
           float* __restrict__ out, int N) {
    extern __shared__ __align__(16) float gdyn[];
    float* s_ms = gdyn;
    float* s_h  = gdyn + HH * GS;
    float* s_wi = gdyn + 2 * HH * GS;
    float* s_wh = s_wi + 2 * 8 * 3 * HH;

    int tid = threadIdx.x;
    int n0 = blockIdx.x * GNS;

    for (int idx = tid; idx < GNS * HH; idx += 256) {
        int i = idx >> 7, k = idx & 127;
        int n = n0 + i;
        float mv = 0.f, hv = 0.f;
        if (n < N) { mv = g_msg[n * HH + k]; hv = h[n * HH + k]; }
        s_ms[k * GS + i] = mv;
        s_h [k * GS + i] = hv;
    }

    int tx = tid & 31;
    int ty = tid >> 5;
    int j = tx * 4;

    u64 ar[4][2], az[4][2], ai[4][2], ah[4][2];
    #pragma unroll
    for (int q = 0; q < 4; q++)
        #pragma unroll
        for (int cp = 0; cp < 2; cp++) {
            ar[q][cp] = 0ull; az[q][cp] = 0ull;
            ai[q][cp] = 0ull; ah[q][cp] = 0ull;
        }

    float4 wi0, wi1, wi2, wh0, wh1, wh2;
    {
        const float4* gi = (const float4*)g_wihT;
        const float4* gh = (const float4*)g_whhT;
        wi0 = gi[tid * 3]; wi1 = gi[tid * 3 + 1]; wi2 = gi[tid * 3 + 2];
        wh0 = gh[tid * 3]; wh1 = gh[tid * 3 + 1]; wh2 = gh[tid * 3 + 2];
        float4* si = (float4*)s_wi;
        float4* sh = (float4*)s_wh;
        si[tid * 3] = wi0; si[tid * 3 + 1] = wi1; si[tid * 3 + 2] = wi2;
        sh[tid * 3] = wh0; sh[tid * 3 + 1] = wh1; sh[tid * 3 + 2] = wh2;
    }
    __syncthreads();

    for (int kt = 0; kt < 16; kt++) {
        int buf = kt & 1;
        if (kt + 1 < 16) {
            const float4* gi = (const float4*)(g_wihT + (kt + 1) * 8 * 3 * HH);
            const float4* gh = (const float4*)(g_whhT + (kt + 1) * 8 * 3 * HH);
            wi0 = gi[tid * 3]; wi1 = gi[tid * 3 + 1]; wi2 = gi[tid * 3 + 2];
            wh0 = gh[tid * 3]; wh1 = gh[tid * 3 + 1]; wh2 = gh[tid * 3 + 2];
        }
        const float* wib = s_wi + buf * (8 * 3 * HH);
        const float* whb = s_wh + buf * (8 * 3 * HH);
        int k0 = kt * 8;
        #pragma unroll
        for (int kk = 0; kk < 8; kk++) {
            int k = k0 + kk;
            u64 md[4], hd[4];
            #pragma unroll
            for (int q = 0; q < 4; q++) {
                md[q] = f2_dup(s_ms[k * GS + ty * 4 + q]);
                hd[q] = f2_dup(s_h [k * GS + ty * 4 + q]);
            }
            const float* wr = &wib[kk * 3 * HH];
            const float* hr = &whb[kk * 3 * HH];
            ulonglong2 wir = *(const ulonglong2*)&wr[j];
            ulonglong2 wiz = *(const ulonglong2*)&wr[HH + j];
            ulonglong2 win = *(const ulonglong2*)&wr[2 * HH + j];
            ulonglong2 whr = *(const ulonglong2*)&hr[j];
            ulonglong2 whz = *(const ulonglong2*)&hr[HH + j];
            ulonglong2 whn = *(const ulonglong2*)&hr[2 * HH + j];
            #pragma unroll
            for (int q = 0; q < 4; q++) {
                f2_fma(ar[q][0], md[q], wir.x); f2_fma(ar[q][0], hd[q], whr.x);
                f2_fma(ar[q][1], md[q], wir.y); f2_fma(ar[q][1], hd[q], whr.y);
                f2_fma(az[q][0], md[q], wiz.x); f2_fma(az[q][0], hd[q], whz.x);
                f2_fma(az[q][1], md[q], wiz.y); f2_fma(az[q][1], hd[q], whz.y);
                f2_fma(ai[q][0], md[q], win.x);
                f2_fma(ai[q][1], md[q], win.y);
                f2_fma(ah[q][0], hd[q], whn.x);
                f2_fma(ah[q][1], hd[q], whn.y);
            }
        }
        if (kt + 1 < 16) {
            float4* si = (float4*)(s_wi + (buf ^ 1) * (8 * 3 * HH));
            float4* sh = (float4*)(s_wh + (buf ^ 1) * (8 * 3 * HH));
            si[tid * 3] = wi0; si[tid * 3 + 1] = wi1; si[tid * 3 + 2] = wi2;
            sh[tid * 3] = wh0; sh[tid * 3 + 1] = wh1; sh[tid * 3 + 2] = wh2;
        }
        __syncthreads();
    }

    #pragma unroll
    for (int q = 0; q < 4; q++) {
        int i = ty * 4 + q;
        int n = n0 + i;
        if (n >= N) continue;
        float sr[4], sz[4], si4[4], sh4[4];
        f2_unpack(ar[q][0], sr[0], sr[1]);  f2_unpack(ar[q][1], sr[2], sr[3]);
        f2_unpack(az[q][0], sz[0], sz[1]);  f2_unpack(az[q][1], sz[2], sz[3]);
        f2_unpack(ai[q][0], si4[0], si4[1]); f2_unpack(ai[q][1], si4[2], si4[3]);
        f2_unpack(ah[q][0], sh4[0], sh4[1]); f2_unpack(ah[q][1], sh4[2], sh4[3]);
        float o[4];
        #pragma unroll
        for (int c = 0; c < 4; c++) {
            int jc = j + c;
            float rg = sr[c] + b_ih[jc] + b_hh[jc];
            rg = 1.f / (1.f + __expf(-rg));
            float zg = sz[c] + b_ih[HH + jc] + b_hh[HH + jc];
            zg = 1.f / (1.f + __expf(-zg));
            float ing = si4[c] + b_ih[2 * HH + jc];
            float hng = sh4[c] + b_hh[2 * HH + jc];
            float ng = tanhf(ing + rg * hng);
            float hv = s_h[jc * GS + i];
            o[c] = (1.f - zg) * ng + zg * hv;
        }
        *(float4*)&out[n * HH + j] = make_float4(o[0], o[1], o[2], o[3]);
    }
}

// ---------------- launch ----------------
extern "C" void kernel_launch(void* const* d_in, const int* in_sizes, int n_in,
                              void* d_out, int out_size) {
    const float* h    = (const float*)d_in[0];
    const int*   ei   = (const int*)  d_in[1];
    const int*   et   = (const int*)  d_in[2];
    const float* ea   = (const float*)d_in[3];
    const float* W1   = (const float*)d_in[4];
    const float* b1   = (const float*)d_in[5];
    const float* W2   = (const float*)d_in[6];
    const float* b2   = (const float*)d_in[7];
    const float* wih  = (const float*)d_in[8];
    const float* whh  = (const float*)d_in[9];
    const float* bih  = (const float*)d_in[10];
    const float* bhh  = (const float*)d_in[11];
    float* out = (float*)d_out;

    int N = in_sizes[0] / HH;   // 50000
    int E = in_sizes[2];        // 800000

    const int mlpSmem = 4 * 128 * KP * (int)sizeof(__nv_bfloat16);   // 155648 B
    const int gruSmem = (2 * HH * GS + 4 * 8 * 3 * HH) * (int)sizeof(float);
    cudaFuncSetAttribute(k_mlp, cudaFuncAttributeMaxDynamicSharedMemorySize, mlpSmem);
    cudaFuncSetAttribute(k_gru, cudaFuncAttributeMaxDynamicSharedMemorySize, gruSmem);

    k_zero<<<2048, 256>>>();
    k_transpose<<<(HH * 3 * HH + 255) / 256, 256>>>(wih, whh);
    {
        int prepN = 2 * TT * 128 * KP;
        k_prepW<<<(prepN + 255) / 256, 256>>>(W1, W2);
    }
    k_hist<<<(E + 255) / 256, 256>>>(et, E);
    k_scan<<<1, 1>>>();
    k_scatter<<<(E + 255) / 256, 256>>>(et, E);

    int mlpGrid = (E + TILE_E - 1) / TILE_E + TT;
    k_mlp<<<mlpGrid, 256, mlpSmem>>>(h, ei, ea, b1, b2, E);

    k_gru<<<(N + GNS - 1) / GNS, 256, gruSmem>>>(h, bih, bhh, out, N);
}

// round 8
// speedup vs baseline: 1.6417x; 1.1786x over previous
#include <cuda_runtime.h>
#include <cuda_bf16.h>
#include <cstdint>

// Problem constants (fixed-shape problem)
#define NN 50000
#define HH 128
#define EE 800000
#define AA 16
#define TT 4
#define HA 144            // H + A
#define TILE_E 128
#define KP 152            // bf16 K stride for A / W1 (pad: ldmatrix conflict-free)
#define KP2 136           // bf16 K stride for W2 (K=128 + pad 8)
#define SF 132            // float staging stride for epilogue2
#define GNS 32            // GRU nodes per CTA
#define GS 33             // padded node stride for GRU staging
#define MLP_CTAS 148

typedef unsigned long long u64;

// ---------------- f32x2 packed-math helpers (GRU) ----------------
__device__ __forceinline__ u64 f2_pack(float lo, float hi) {
    u64 r;
    asm("mov.b64 %0, {%1,%2};" : "=l"(r)
        : "r"(__float_as_uint(lo)), "r"(__float_as_uint(hi)));
    return r;
}
__device__ __forceinline__ u64 f2_dup(float v) { return f2_pack(v, v); }
__device__ __forceinline__ void f2_fma(u64& d, u64 a, u64 b) {
    asm("fma.rn.f32x2 %0, %1, %2, %0;" : "+l"(d) : "l"(a), "l"(b));
}
__device__ __forceinline__ void f2_unpack(u64 v, float& lo, float& hi) {
    unsigned int l, h;
    asm("mov.b64 {%0,%1}, %2;" : "=r"(l), "=r"(h) : "l"(v));
    lo = __uint_as_float(l); hi = __uint_as_float(h);
}

// ---------------- mma.sync helpers ----------------
__device__ __forceinline__ uint32_t smem_u32(const void* p) {
    uint32_t a;
    asm("{ .reg .u64 t; cvta.to.shared.u64 t, %1; cvt.u32.u64 %0, t; }"
        : "=r"(a) : "l"(p));
    return a;
}
__device__ __forceinline__ void ldsm4(uint32_t& r0, uint32_t& r1,
                                      uint32_t& r2, uint32_t& r3, uint32_t addr) {
    asm volatile("ldmatrix.sync.aligned.m8n8.x4.shared.b16 {%0,%1,%2,%3}, [%4];"
                 : "=r"(r0), "=r"(r1), "=r"(r2), "=r"(r3) : "r"(addr));
}
__device__ __forceinline__ void mma16816(float* d, const uint32_t* a, const uint32_t* b) {
    asm volatile("mma.sync.aligned.m16n8k16.row.col.f32.bf16.bf16.f32 "
                 "{%0,%1,%2,%3},{%4,%5,%6,%7},{%8,%9},{%0,%1,%2,%3};"
                 : "+f"(d[0]), "+f"(d[1]), "+f"(d[2]), "+f"(d[3])
                 : "r"(a[0]), "r"(a[1]), "r"(a[2]), "r"(a[3]),
                   "r"(b[0]), "r"(b[1]));
}
__device__ __forceinline__ void red4(float* p, float4 v) {
    asm volatile("red.global.add.v4.f32 [%0], {%1,%2,%3,%4};"
                 :: "l"(p), "f"(v.x), "f"(v.y), "f"(v.z), "f"(v.w) : "memory");
}

// bf16 hi/lo split of a float
__device__ __forceinline__ void bf_split(float v, __nv_bfloat16& hi, __nv_bfloat16& lo) {
    hi = __float2bfloat16(v);
    lo = __float2bfloat16(v - __bfloat162float(hi));
}

// ---------------- device scratch ----------------
__device__ float g_msg[NN * HH];
__device__ int   g_bucket[EE];
__device__ int   g_cnt[TT];
__device__ int   g_cur[TT];
__device__ int   g_off[TT + 1];
__device__ int   g_ctaStart[TT + 1];
__device__ float g_wihT[HH * 3 * HH];
__device__ float g_whhT[HH * 3 * HH];
// bf16 weight images, W^T [N=128][stride] row-major, hi/lo splits
__device__ __align__(16) __nv_bfloat16 g_W1b[TT][2][128 * KP];
__device__ __align__(16) __nv_bfloat16 g_W2b[TT][2][128 * KP2];

// ---------------- utility kernels ----------------
__global__ void k_zero() {
    int idx = blockIdx.x * blockDim.x + threadIdx.x;
    int stride = gridDim.x * blockDim.x;
    float4* p = reinterpret_cast<float4*>(g_msg);
    int total4 = NN * HH / 4;
    float4 z = make_float4(0.f, 0.f, 0.f, 0.f);
    for (int i = idx; i < total4; i += stride) p[i] = z;
    if (idx < TT) g_cnt[idx] = 0;
}

__global__ void k_transpose(const float* __restrict__ wih,
                            const float* __restrict__ whh) {
    int idx = blockIdx.x * blockDim.x + threadIdx.x;
    if (idx < HH * 3 * HH) {
        int k = idx / (3 * HH);
        int g = idx % (3 * HH);
        g_wihT[idx] = wih[g * HH + k];
        g_whhT[idx] = whh[g * HH + k];
    }
}

// Build bf16 hi/lo images of W1^T, W2^T as [n][k] row-major.
__global__ void k_prepW(const float* __restrict__ W1, const float* __restrict__ W2) {
    int idx = blockIdx.x * blockDim.x + threadIdx.x;
    const int per1 = 128 * KP;
    const int per2 = 128 * KP2;
    if (idx < TT * per1) {
        int t = idx / per1;
        int rem = idx % per1;
        int n = rem / KP, k = rem % KP;
        float v = (k < HA) ? W1[(t * HA + k) * HH + n] : 0.f;
        __nv_bfloat16 hi, lo; bf_split(v, hi, lo);
        g_W1b[t][0][n * KP + k] = hi;
        g_W1b[t][1][n * KP + k] = lo;
    } else if (idx < TT * per1 + TT * per2) {
        int j = idx - TT * per1;
        int t = j / per2;
        int rem = j % per2;
        int n = rem / KP2, k = rem % KP2;
        float v = (k < HH) ? W2[(t * HH + k) * HH + n] : 0.f;
        __nv_bfloat16 hi, lo; bf_split(v, hi, lo);
        g_W2b[t][0][n * KP2 + k] = hi;
        g_W2b[t][1][n * KP2 + k] = lo;
    }
}

__global__ void k_hist(const int* __restrict__ et, int E) {
    __shared__ int c[TT];
    if (threadIdx.x < TT) c[threadIdx.x] = 0;
    __syncthreads();
    int i = blockIdx.x * blockDim.x + threadIdx.x;
    if (i < E) atomicAdd(&c[et[i]], 1);
    __syncthreads();
    if (threadIdx.x < TT && c[threadIdx.x] > 0)
        atomicAdd(&g_cnt[threadIdx.x], c[threadIdx.x]);
}

__global__ void k_scan() {
    int off = 0;
    int nt[TT];
    int tot = 0;
    for (int t = 0; t < TT; t++) {
        g_off[t] = off;
        g_cur[t] = off;
        off += g_cnt[t];
        nt[t] = (g_cnt[t] + TILE_E - 1) / TILE_E;
        tot += nt[t];
    }
    g_off[TT] = off;
    // partition MLP_CTAS CTAs across types, proportional to tile counts
    int c[TT]; int used = 0;
    for (int t = 0; t < TT; t++) {
        c[t] = (nt[t] > 0 && tot > 0)
             ? (int)(((long long)MLP_CTAS * nt[t]) / tot) : 0;
        if (nt[t] > 0 && c[t] < 1) c[t] = 1;
        used += c[t];
    }
    while (used > MLP_CTAS) {   // shrink largest
        int a = 0;
        for (int t = 1; t < TT; t++) if (c[t] > c[a]) a = t;
        c[a]--; used--;
    }
    int guard = 0;
    while (used < MLP_CTAS && guard < 1000) {   // distribute leftover
        for (int t = 0; t < TT && used < MLP_CTAS; t++)
            if (nt[t] > 0) { c[t]++; used++; }
        guard++;
        bool any = false;
        for (int t = 0; t < TT; t++) any |= (nt[t] > 0);
        if (!any) break;
    }
    int s = 0;
    for (int t = 0; t < TT; t++) { g_ctaStart[t] = s; s += c[t]; }
    g_ctaStart[TT] = s;
}

__global__ void k_scatter(const int* __restrict__ et, int E) {
    __shared__ int c[TT], base[TT];
    if (threadIdx.x < TT) c[threadIdx.x] = 0;
    __syncthreads();
    int i = blockIdx.x * blockDim.x + threadIdx.x;
    int t = 0, pos = 0;
    bool valid = (i < E);
    if (valid) {
        t = et[i];
        pos = atomicAdd(&c[t], 1);
    }
    __syncthreads();
    if (threadIdx.x < TT)
        base[threadIdx.x] = (c[threadIdx.x] > 0)
            ? atomicAdd(&g_cur[threadIdx.x], c[threadIdx.x]) : 0;
    __syncthreads();
    if (valid) g_bucket[base[t] + pos] = i;
}

// ---------------- bf16-split warp GEMM core ----------------
// Warp computes D[32 x 64] at (m0, n0). A row-major [128][KP] bf16 in smem,
// B row-major [128][BST] bf16 ([n][k], k contiguous). Plain ldmatrix both.
template <int KSTEPS, int BST>
__device__ __forceinline__ void gemm_split(uint32_t aHi, uint32_t aLo,
                                           uint32_t bHi, uint32_t bLo,
                                           int lane, int m0, int n0,
                                           float d[2][8][4]) {
    uint32_t aRow = (uint32_t)(lane & 15);
    uint32_t aK   = (uint32_t)((lane >> 4) << 3);
    uint32_t bRow = (uint32_t)((lane & 7) + ((lane >> 4) << 3));
    uint32_t bK   = (uint32_t)(((lane >> 3) & 1) << 3);
    uint32_t aOff0 = ((uint32_t)(m0 + aRow) * KP + aK) * 2;
    uint32_t aOff1 = aOff0 + 16 * KP * 2;
    uint32_t bOff[4];
    #pragma unroll
    for (int j = 0; j < 4; j++)
        bOff[j] = ((uint32_t)(n0 + j * 16 + bRow) * BST + bK) * 2;

    #pragma unroll 1
    for (int ks = 0; ks < KSTEPS; ks++) {
        uint32_t kb = (uint32_t)ks * 32;   // 16 bf16 = 32 bytes
        uint32_t ah[2][4], al[2][4];
        ldsm4(ah[0][0], ah[0][1], ah[0][2], ah[0][3], aHi + aOff0 + kb);
        ldsm4(ah[1][0], ah[1][1], ah[1][2], ah[1][3], aHi + aOff1 + kb);
        ldsm4(al[0][0], al[0][1], al[0][2], al[0][3], aLo + aOff0 + kb);
        ldsm4(al[1][0], al[1][1], al[1][2], al[1][3], aLo + aOff1 + kb);
        uint32_t bh[8][2], bl[8][2];
        #pragma unroll
        for (int j = 0; j < 4; j++) {
            uint32_t r0, r1, r2, r3;
            ldsm4(r0, r1, r2, r3, bHi + bOff[j] + kb);
            bh[2 * j][0] = r0; bh[2 * j][1] = r1;
            bh[2 * j + 1][0] = r2; bh[2 * j + 1][1] = r3;
            ldsm4(r0, r1, r2, r3, bLo + bOff[j] + kb);
            bl[2 * j][0] = r0; bl[2 * j][1] = r1;
            bl[2 * j + 1][0] = r2; bl[2 * j + 1][1] = r3;
        }
        #pragma unroll
        for (int mt = 0; mt < 2; mt++)
            #pragma unroll
            for (int nt = 0; nt < 8; nt++) {
                mma16816(d[mt][nt], ah[mt], bh[nt]);
                mma16816(d[mt][nt], ah[mt], bl[nt]);
                mma16816(d[mt][nt], al[mt], bh[nt]);
            }
    }
}

// ---------------- persistent edge MLP via mma.sync bf16 hi/lo split --------
// 148 CTAs, each bound to one edge type; weights resident in smem; loops tiles.
// dyn smem: A_hi | A_lo | W1_hi | W1_lo | W2_hi | W2_lo  (225280 B)
__global__ __launch_bounds__(256, 1)
void k_mlp(const float* __restrict__ h,
           const int*   __restrict__ ei,
           const float* __restrict__ ea,
           const float* __restrict__ b1,
           const float* __restrict__ b2,
           int E) {
    extern __shared__ __align__(16) char dsm[];
    __nv_bfloat16* sAhi  = (__nv_bfloat16*)dsm;
    __nv_bfloat16* sAlo  = sAhi + 128 * KP;
    __nv_bfloat16* sB1hi = sAlo + 128 * KP;
    __nv_bfloat16* sB1lo = sB1hi + 128 * KP;
    __nv_bfloat16* sB2hi = sB1lo + 128 * KP;
    __nv_bfloat16* sB2lo = sB2hi + 128 * KP2;
    float* stagef = (float*)dsm;       // epilogue2 staging (reuses A region)

    __shared__ int s_dst[TILE_E], s_src[TILE_E], s_eid[TILE_E];
    __shared__ float s_b1[HH], s_b2[HH];

    int tid = threadIdx.x;
    int wid = tid >> 5;
    int lane = tid & 31;

    int b = blockIdx.x;
    int cs1 = g_ctaStart[1], cs2 = g_ctaStart[2],
        cs3 = g_ctaStart[3], cs4 = g_ctaStart[4];
    if (b >= cs4) return;
    int t;
    if      (b < cs1) t = 0;
    else if (b < cs2) t = 1;
    else if (b < cs3) t = 2;
    else              t = 3;
    int csBase = (t == 0) ? 0 : (t == 1) ? cs1 : (t == 2) ? cs2 : cs3;
    int csEnd  = (t == 0) ? cs1 : (t == 1) ? cs2 : (t == 2) ? cs3 : cs4;
    int myIdx = b - csBase;
    int nCtas = csEnd - csBase;

    int typeOff = g_off[t];
    int typeCnt = g_off[t + 1] - typeOff;
    int nTiles = (typeCnt + TILE_E - 1) / TILE_E;

    // ---- one-time loads: biases + resident weight images ----
    for (int i = tid; i < HH; i += 256) {
        s_b1[i] = b1[t * HH + i];
        s_b2[i] = b2[t * HH + i];
    }
    {
        const int n41 = 128 * KP * 2 / 16;    // 2432 float4 per image
        const float4* w1h = (const float4*)&g_W1b[t][0][0];
        const float4* w1l = (const float4*)&g_W1b[t][1][0];
        float4* d1h = (float4*)sB1hi;
        float4* d1l = (float4*)sB1lo;
        for (int i = tid; i < n41; i += 256) { d1h[i] = w1h[i]; d1l[i] = w1l[i]; }
        const int n42 = 128 * KP2 * 2 / 16;   // 2176 float4 per image
        const float4* w2h = (const float4*)&g_W2b[t][0][0];
        const float4* w2l = (const float4*)&g_W2b[t][1][0];
        float4* d2h = (float4*)sB2hi;
        float4* d2l = (float4*)sB2lo;
        for (int i = tid; i < n42; i += 256) { d2h[i] = w2h[i]; d2l[i] = w2l[i]; }
    }
    __syncthreads();

    uint32_t aHi = smem_u32(sAhi), aLo = smem_u32(sAlo);
    uint32_t b1Hi = smem_u32(sB1hi), b1Lo = smem_u32(sB1lo);
    uint32_t b2Hi = smem_u32(sB2hi), b2Lo = smem_u32(sB2lo);
    int m0 = (wid & 3) * 32;
    int n0 = (wid >> 2) * 64;

    const int* srcp = ei;
    const int* dstp = ei + E;

    // ---- persistent tile loop ----
    for (int tile = myIdx; tile < nTiles; tile += nCtas) {
        int segBase = typeOff + tile * TILE_E;
        int segCnt = typeCnt - tile * TILE_E;
        if (segCnt > TILE_E) segCnt = TILE_E;

        // edge metadata
        for (int i = tid; i < TILE_E; i += 256) {
            if (i < segCnt) {
                int e = g_bucket[segBase + i];
                s_eid[i] = e; s_src[i] = srcp[e]; s_dst[i] = dstp[e];
            } else {
                s_eid[i] = 0; s_src[i] = 0; s_dst[i] = -1;
            }
        }
        __syncthreads();

        // gather x -> bf16 hi/lo into A buffers (warp per edge row)
        for (int i = wid; i < TILE_E; i += 8) {
            bool valid = (i < segCnt);
            int sidx = s_src[i], e = s_eid[i];
            #pragma unroll
            for (int c = 0; c < 4; c++) {
                int j = lane + 32 * c;
                float v = valid ? h[sidx * HH + j] : 0.f;
                __nv_bfloat16 hi, lo; bf_split(v, hi, lo);
                sAhi[i * KP + j] = hi; sAlo[i * KP + j] = lo;
            }
            if (lane < AA) {
                int j = HH + lane;
                float v = valid ? ea[e * AA + lane] : 0.f;
                __nv_bfloat16 hi, lo; bf_split(v, hi, lo);
                sAhi[i * KP + j] = hi; sAlo[i * KP + j] = lo;
            }
        }
        __syncthreads();

        float d[2][8][4];
        #pragma unroll
        for (int mt = 0; mt < 2; mt++)
            #pragma unroll
            for (int nt = 0; nt < 8; nt++)
                #pragma unroll
                for (int q = 0; q < 4; q++) d[mt][nt][q] = 0.f;

        // ---- GEMM1: K = 144 (9 k-steps) ----
        gemm_split<9, KP>(aHi, aLo, b1Hi, b1Lo, lane, m0, n0, d);
        __syncthreads();

        // epilogue 1: relu(d + b1) -> hi/lo bf16 back into A buffers
        {
            int rbase = m0 + (lane >> 2);
            int cbase = n0 + 2 * (lane & 3);
            #pragma unroll
            for (int mt = 0; mt < 2; mt++) {
                #pragma unroll
                for (int nt = 0; nt < 8; nt++) {
                    int col = cbase + nt * 8;
                    float bb0 = s_b1[col], bb1 = s_b1[col + 1];
                    #pragma unroll
                    for (int half = 0; half < 2; half++) {
                        int r = rbase + mt * 16 + half * 8;
                        float v0 = fmaxf(d[mt][nt][2 * half] + bb0, 0.f);
                        float v1 = fmaxf(d[mt][nt][2 * half + 1] + bb1, 0.f);
                        __nv_bfloat16 h0, l0, h1, l1;
                        bf_split(v0, h0, l0); bf_split(v1, h1, l1);
                        __nv_bfloat162 hp(h0, h1), lp(l0, l1);
                        *(uint32_t*)&sAhi[r * KP + col] = *(uint32_t*)&hp;
                        *(uint32_t*)&sAlo[r * KP + col] = *(uint32_t*)&lp;
                        d[mt][nt][2 * half] = 0.f;
                        d[mt][nt][2 * half + 1] = 0.f;
                    }
                }
            }
        }
        __syncthreads();

        // ---- GEMM2: K = 128 (8 k-steps) ----
        gemm_split<8, KP2>(aHi, aLo, b2Hi, b2Lo, lane, m0, n0, d);
        __syncthreads();   // done reading A before staging overwrites it

        // epilogue 2: stage d + b2 as fp32
        {
            int rbase = m0 + (lane >> 2);
            int cbase = n0 + 2 * (lane & 3);
            #pragma unroll
            for (int mt = 0; mt < 2; mt++) {
                #pragma unroll
                for (int nt = 0; nt < 8; nt++) {
                    int col = cbase + nt * 8;
                    float bb0 = s_b2[col], bb1 = s_b2[col + 1];
                    #pragma unroll
                    for (int half = 0; half < 2; half++) {
                        int r = rbase + mt * 16 + half * 8;
                        stagef[r * SF + col]     = d[mt][nt][2 * half] + bb0;
                        stagef[r * SF + col + 1] = d[mt][nt][2 * half + 1] + bb1;
                    }
                }
            }
        }
        __syncthreads();

        // coalesced scatter-add flush: warp per edge row, red.v4 per lane
        for (int i = wid; i < TILE_E; i += 8) {
            int dstn = s_dst[i];
            if (dstn < 0) continue;
            float4 v = *(float4*)&stagef[i * SF + lane * 4];
            red4(&g_msg[dstn * HH + lane * 4], v);
        }
        __syncthreads();   // stage/A reused next iteration
    }
}

// ---------------- fused GRU cell (f32x2) ----------------
__global__ __launch_bounds__(256, 2)
void k_gru(const float* __restrict__ h,
           const float* __restrict__ b_ih,
           const float* __restrict__ b_hh,
           float* __restrict__ out, int N) {
    extern __shared__ __align__(16) float gdyn[];
    float* s_ms = gdyn;
    float* s_h  = gdyn + HH * GS;
    float* s_wi = gdyn + 2 * HH * GS;
    float* s_wh = s_wi + 2 * 8 * 3 * HH;

    int tid = threadIdx.x;
    int n0 = blockIdx.x * GNS;

    for (int idx = tid; idx < GNS * HH; idx += 256) {
        int i = idx >> 7, k = idx & 127;
        int n = n0 + i;
        float mv = 0.f, hv = 0.f;
        if (n < N) { mv = g_msg[n * HH + k]; hv = h[n * HH + k]; }
        s_ms[k * GS + i] = mv;
        s_h [k * GS + i] = hv;
    }

    int tx = tid & 31;
    int ty = tid >> 5;
    int j = tx * 4;

    u64 ar[4][2], az[4][2], ai[4][2], ah[4][2];
    #pragma unroll
    for (int q = 0; q < 4; q++)
        #pragma unroll
        for (int cp = 0; cp < 2; cp++) {
            ar[q][cp] = 0ull; az[q][cp] = 0ull;
            ai[q][cp] = 0ull; ah[q][cp] = 0ull;
        }

    float4 wi0, wi1, wi2, wh0, wh1, wh2;
    {
        const float4* gi = (const float4*)g_wihT;
        const float4* gh = (const float4*)g_whhT;
        wi0 = gi[tid * 3]; wi1 = gi[tid * 3 + 1]; wi2 = gi[tid * 3 + 2];
        wh0 = gh[tid * 3]; wh1 = gh[tid * 3 + 1]; wh2 = gh[tid * 3 + 2];
        float4* si = (float4*)s_wi;
        float4* sh = (float4*)s_wh;
        si[tid * 3] = wi0; si[tid * 3 + 1] = wi1; si[tid * 3 + 2] = wi2;
        sh[tid * 3] = wh0; sh[tid * 3 + 1] = wh1; sh[tid * 3 + 2] = wh2;
    }
    __syncthreads();

    for (int kt = 0; kt < 16; kt++) {
        int buf = kt & 1;
        if (kt + 1 < 16) {
            const float4* gi = (const float4*)(g_wihT + (kt + 1) * 8 * 3 * HH);
            const float4* gh = (const float4*)(g_whhT + (kt + 1) * 8 * 3 * HH);
            wi0 = gi[tid * 3]; wi1 = gi[tid * 3 + 1]; wi2 = gi[tid * 3 + 2];
            wh0 = gh[tid * 3]; wh1 = gh[tid * 3 + 1]; wh2 = gh[tid * 3 + 2];
        }
        const float* wib = s_wi + buf * (8 * 3 * HH);
        const float* whb = s_wh + buf * (8 * 3 * HH);
        int k0 = kt * 8;
        #pragma unroll
        for (int kk = 0; kk < 8; kk++) {
            int k = k0 + kk;
            u64 md[4], hd[4];
            #pragma unroll
            for (int q = 0; q < 4; q++) {
                md[q] = f2_dup(s_ms[k * GS + ty * 4 + q]);
                hd[q] = f2_dup(s_h [k * GS + ty * 4 + q]);
            }
            const float* wr = &wib[kk * 3 * HH];
            const float* hr = &whb[kk * 3 * HH];
            ulonglong2 wir = *(const ulonglong2*)&wr[j];
            ulonglong2 wiz = *(const ulonglong2*)&wr[HH + j];
            ulonglong2 win = *(const ulonglong2*)&wr[2 * HH + j];
            ulonglong2 whr = *(const ulonglong2*)&hr[j];
            ulonglong2 whz = *(const ulonglong2*)&hr[HH + j];
            ulonglong2 whn = *(const ulonglong2*)&hr[2 * HH + j];
            #pragma unroll
            for (int q = 0; q < 4; q++) {
                f2_fma(ar[q][0], md[q], wir.x); f2_fma(ar[q][0], hd[q], whr.x);
                f2_fma(ar[q][1], md[q], wir.y); f2_fma(ar[q][1], hd[q], whr.y);
                f2_fma(az[q][0], md[q], wiz.x); f2_fma(az[q][0], hd[q], whz.x);
                f2_fma(az[q][1], md[q], wiz.y); f2_fma(az[q][1], hd[q], whz.y);
                f2_fma(ai[q][0], md[q], win.x);
                f2_fma(ai[q][1], md[q], win.y);
                f2_fma(ah[q][0], hd[q], whn.x);
                f2_fma(ah[q][1], hd[q], whn.y);
            }
        }
        if (kt + 1 < 16) {
            float4* si = (float4*)(s_wi + (buf ^ 1) * (8 * 3 * HH));
            float4* sh = (float4*)(s_wh + (buf ^ 1) * (8 * 3 * HH));
            si[tid * 3] = wi0; si[tid * 3 + 1] = wi1; si[tid * 3 + 2] = wi2;
            sh[tid * 3] = wh0; sh[tid * 3 + 1] = wh1; sh[tid * 3 + 2] = wh2;
        }
        __syncthreads();
    }

    #pragma unroll
    for (int q = 0; q < 4; q++) {
        int i = ty * 4 + q;
        int n = n0 + i;
        if (n >= N) continue;
        float sr[4], sz[4], si4[4], sh4[4];
        f2_unpack(ar[q][0], sr[0], sr[1]);  f2_unpack(ar[q][1], sr[2], sr[3]);
        f2_unpack(az[q][0], sz[0], sz[1]);  f2_unpack(az[q][1], sz[2], sz[3]);
        f2_unpack(ai[q][0], si4[0], si4[1]); f2_unpack(ai[q][1], si4[2], si4[3]);
        f2_unpack(ah[q][0], sh4[0], sh4[1]); f2_unpack(ah[q][1], sh4[2], sh4[3]);
        float o[4];
        #pragma unroll
        for (int c = 0; c < 4; c++) {
            int jc = j + c;
            float rg = sr[c] + b_ih[jc] + b_hh[jc];
            rg = 1.f / (1.f + __expf(-rg));
            float zg = sz[c] + b_ih[HH + jc] + b_hh[HH + jc];
            zg = 1.f / (1.f + __expf(-zg));
            float ing = si4[c] + b_ih[2 * HH + jc];
            float hng = sh4[c] + b_hh[2 * HH + jc];
            float ng = tanhf(ing + rg * hng);
            float hv = s_h[jc * GS + i];
            o[c] = (1.f - zg) * ng + zg * hv;
        }
        *(float4*)&out[n * HH + j] = make_float4(o[0], o[1], o[2], o[3]);
    }
}

// ---------------- launch ----------------
extern "C" void kernel_launch(void* const* d_in, const int* in_sizes, int n_in,
                              void* d_out, int out_size) {
    const float* h    = (const float*)d_in[0];
    const int*   ei   = (const int*)  d_in[1];
    const int*   et   = (const int*)  d_in[2];
    const float* ea   = (const float*)d_in[3];
    const float* W1   = (const float*)d_in[4];
    const float* b1   = (const float*)d_in[5];
    const float* W2   = (const float*)d_in[6];
    const float* b2   = (const float*)d_in[7];
    const float* wih  = (const float*)d_in[8];
    const float* whh  = (const float*)d_in[9];
    const float* bih  = (const float*)d_in[10];
    const float* bhh  = (const float*)d_in[11];
    float* out = (float*)d_out;

    int N = in_sizes[0] / HH;   // 50000
    int E = in_sizes[2];        // 800000

    const int mlpSmem = (4 * 128 * KP + 2 * 128 * KP2) * (int)sizeof(__nv_bfloat16); // 225280
    const int gruSmem = (2 * HH * GS + 4 * 8 * 3 * HH) * (int)sizeof(float);
    cudaFuncSetAttribute(k_mlp, cudaFuncAttributeMaxDynamicSharedMemorySize, mlpSmem);
    cudaFuncSetAttribute(k_gru, cudaFuncAttributeMaxDynamicSharedMemorySize, gruSmem);

    k_zero<<<2048, 256>>>();
    k_transpose<<<(HH * 3 * HH + 255) / 256, 256>>>(wih, whh);
    {
        int prepN = TT * 128 * KP + TT * 128 * KP2;
        k_prepW<<<(prepN + 255) / 256, 256>>>(W1, W2);
    }
    k_hist<<<(E + 255) / 256, 256>>>(et, E);
    k_scan<<<1, 1>>>();
    k_scatter<<<(E + 255) / 256, 256>>>(et, E);

    k_mlp<<<MLP_CTAS, 256, mlpSmem>>>(h, ei, ea, b1, b2, E);

    k_gru<<<(N + GNS - 1) / GNS, 256, gruSmem>>>(h, bih, bhh, out, N);
}

// round 9
// speedup vs baseline: 1.9560x; 1.1915x over previous
#include <cuda_runtime.h>
#include <cuda_bf16.h>
#include <cstdint>

// Problem constants (fixed-shape problem)
#define NN 50000
#define HH 128
#define EE 800000
#define AA 16
#define TT 4
#define HA 144            // H + A
#define TILE_E 128
#define KP 152            // bf16 K stride for A / W1 (pad: ldmatrix conflict-free)
#define KP2 136           // bf16 K stride for W2 (K=128 + pad 8)
#define SF 132            // float staging stride for epilogue2
#define GNS 32            // GRU nodes per CTA
#define GS 33             // padded node stride for GRU staging
#define MLP_CTAS 148
#define MLP_THREADS 512

typedef unsigned long long u64;

// ---------------- f32x2 packed-math helpers (GRU) ----------------
__device__ __forceinline__ u64 f2_pack(float lo, float hi) {
    u64 r;
    asm("mov.b64 %0, {%1,%2};" : "=l"(r)
        : "r"(__float_as_uint(lo)), "r"(__float_as_uint(hi)));
    return r;
}
__device__ __forceinline__ u64 f2_dup(float v) { return f2_pack(v, v); }
__device__ __forceinline__ void f2_fma(u64& d, u64 a, u64 b) {
    asm("fma.rn.f32x2 %0, %1, %2, %0;" : "+l"(d) : "l"(a), "l"(b));
}
__device__ __forceinline__ void f2_unpack(u64 v, float& lo, float& hi) {
    unsigned int l, h;
    asm("mov.b64 {%0,%1}, %2;" : "=r"(l), "=r"(h) : "l"(v));
    lo = __uint_as_float(l); hi = __uint_as_float(h);
}

// ---------------- mma.sync helpers ----------------
__device__ __forceinline__ uint32_t smem_u32(const void* p) {
    uint32_t a;
    asm("{ .reg .u64 t; cvta.to.shared.u64 t, %1; cvt.u32.u64 %0, t; }"
        : "=r"(a) : "l"(p));
    return a;
}
__device__ __forceinline__ void ldsm4(uint32_t& r0, uint32_t& r1,
                                      uint32_t& r2, uint32_t& r3, uint32_t addr) {
    asm volatile("ldmatrix.sync.aligned.m8n8.x4.shared.b16 {%0,%1,%2,%3}, [%4];"
                 : "=r"(r0), "=r"(r1), "=r"(r2), "=r"(r3) : "r"(addr));
}
__device__ __forceinline__ void mma16816(float* d, const uint32_t* a, const uint32_t* b) {
    asm volatile("mma.sync.aligned.m16n8k16.row.col.f32.bf16.bf16.f32 "
                 "{%0,%1,%2,%3},{%4,%5,%6,%7},{%8,%9},{%0,%1,%2,%3};"
                 : "+f"(d[0]), "+f"(d[1]), "+f"(d[2]), "+f"(d[3])
                 : "r"(a[0]), "r"(a[1]), "r"(a[2]), "r"(a[3]),
                   "r"(b[0]), "r"(b[1]));
}
__device__ __forceinline__ void red4(float* p, float4 v) {
    asm volatile("red.global.add.v4.f32 [%0], {%1,%2,%3,%4};"
                 :: "l"(p), "f"(v.x), "f"(v.y), "f"(v.z), "f"(v.w) : "memory");
}

// bf16 hi/lo split of a float
__device__ __forceinline__ void bf_split(float v, __nv_bfloat16& hi, __nv_bfloat16& lo) {
    hi = __float2bfloat16(v);
    lo = __float2bfloat16(v - __bfloat162float(hi));
}
// split 2 floats -> packed bf16x2 hi word + lo word
__device__ __forceinline__ void bf_split2(float v0, float v1, uint32_t& hw, uint32_t& lw) {
    __nv_bfloat16 h0, l0, h1, l1;
    bf_split(v0, h0, l0); bf_split(v1, h1, l1);
    __nv_bfloat162 hp(h0, h1), lp(l0, l1);
    hw = *(uint32_t*)&hp; lw = *(uint32_t*)&lp;
}

// ---------------- device scratch ----------------
__device__ float g_msg[NN * HH];
__device__ int   g_bucket[EE];
__device__ int   g_cnt[TT];
__device__ int   g_cur[TT];
__device__ int   g_off[TT + 1];
__device__ int   g_ctaStart[TT + 1];
__device__ float g_wihT[HH * 3 * HH];
__device__ float g_whhT[HH * 3 * HH];
// bf16 weight images, W^T [N=128][stride] row-major, hi/lo splits
__device__ __align__(16) __nv_bfloat16 g_W1b[TT][2][128 * KP];
__device__ __align__(16) __nv_bfloat16 g_W2b[TT][2][128 * KP2];

// ---------------- utility kernels ----------------
__global__ void k_zero() {
    int idx = blockIdx.x * blockDim.x + threadIdx.x;
    int stride = gridDim.x * blockDim.x;
    float4* p = reinterpret_cast<float4*>(g_msg);
    int total4 = NN * HH / 4;
    float4 z = make_float4(0.f, 0.f, 0.f, 0.f);
    for (int i = idx; i < total4; i += stride) p[i] = z;
    if (idx < TT) g_cnt[idx] = 0;
}

__global__ void k_transpose(const float* __restrict__ wih,
                            const float* __restrict__ whh) {
    int idx = blockIdx.x * blockDim.x + threadIdx.x;
    if (idx < HH * 3 * HH) {
        int k = idx / (3 * HH);
        int g = idx % (3 * HH);
        g_wihT[idx] = wih[g * HH + k];
        g_whhT[idx] = whh[g * HH + k];
    }
}

// Build bf16 hi/lo images of W1^T, W2^T as [n][k] row-major.
__global__ void k_prepW(const float* __restrict__ W1, const float* __restrict__ W2) {
    int idx = blockIdx.x * blockDim.x + threadIdx.x;
    const int per1 = 128 * KP;
    const int per2 = 128 * KP2;
    if (idx < TT * per1) {
        int t = idx / per1;
        int rem = idx % per1;
        int n = rem / KP, k = rem % KP;
        float v = (k < HA) ? W1[(t * HA + k) * HH + n] : 0.f;
        __nv_bfloat16 hi, lo; bf_split(v, hi, lo);
        g_W1b[t][0][n * KP + k] = hi;
        g_W1b[t][1][n * KP + k] = lo;
    } else if (idx < TT * per1 + TT * per2) {
        int j = idx - TT * per1;
        int t = j / per2;
        int rem = j % per2;
        int n = rem / KP2, k = rem % KP2;
        float v = (k < HH) ? W2[(t * HH + k) * HH + n] : 0.f;
        __nv_bfloat16 hi, lo; bf_split(v, hi, lo);
        g_W2b[t][0][n * KP2 + k] = hi;
        g_W2b[t][1][n * KP2 + k] = lo;
    }
}

__global__ void k_hist(const int* __restrict__ et, int E) {
    __shared__ int c[TT];
    if (threadIdx.x < TT) c[threadIdx.x] = 0;
    __syncthreads();
    int i = blockIdx.x * blockDim.x + threadIdx.x;
    if (i < E) atomicAdd(&c[et[i]], 1);
    __syncthreads();
    if (threadIdx.x < TT && c[threadIdx.x] > 0)
        atomicAdd(&g_cnt[threadIdx.x], c[threadIdx.x]);
}

__global__ void k_scan() {
    int off = 0;
    int nt[TT];
    int tot = 0;
    for (int t = 0; t < TT; t++) {
        g_off[t] = off;
        g_cur[t] = off;
        off += g_cnt[t];
        nt[t] = (g_cnt[t] + TILE_E - 1) / TILE_E;
        tot += nt[t];
    }
    g_off[TT] = off;
    int c[TT]; int used = 0;
    for (int t = 0; t < TT; t++) {
        c[t] = (nt[t] > 0 && tot > 0)
             ? (int)(((long long)MLP_CTAS * nt[t]) / tot) : 0;
        if (nt[t] > 0 && c[t] < 1) c[t] = 1;
        used += c[t];
    }
    while (used > MLP_CTAS) {
        int a = 0;
        for (int t = 1; t < TT; t++) if (c[t] > c[a]) a = t;
        c[a]--; used--;
    }
    int guard = 0;
    while (used < MLP_CTAS && guard < 1000) {
        for (int t = 0; t < TT && used < MLP_CTAS; t++)
            if (nt[t] > 0) { c[t]++; used++; }
        guard++;
        bool any = false;
        for (int t = 0; t < TT; t++) any |= (nt[t] > 0);
        if (!any) break;
    }
    int s = 0;
    for (int t = 0; t < TT; t++) { g_ctaStart[t] = s; s += c[t]; }
    g_ctaStart[TT] = s;
}

__global__ void k_scatter(const int* __restrict__ et, int E) {
    __shared__ int c[TT], base[TT];
    if (threadIdx.x < TT) c[threadIdx.x] = 0;
    __syncthreads();
    int i = blockIdx.x * blockDim.x + threadIdx.x;
    int t = 0, pos = 0;
    bool valid = (i < E);
    if (valid) {
        t = et[i];
        pos = atomicAdd(&c[t], 1);
    }
    __syncthreads();
    if (threadIdx.x < TT)
        base[threadIdx.x] = (c[threadIdx.x] > 0)
            ? atomicAdd(&g_cur[threadIdx.x], c[threadIdx.x]) : 0;
    __syncthreads();
    if (valid) g_bucket[base[t] + pos] = i;
}

// ---------------- bf16-split warp GEMM core (32x32 warp tile) -------------
// Warp computes D[32 x 32] at (m0, n0). A row-major [128][KP] bf16 in smem,
// B row-major [128][BST] bf16 ([n][k], k contiguous). Plain ldmatrix both.
template <int KSTEPS, int BST>
__device__ __forceinline__ void gemm_split(uint32_t aHi, uint32_t aLo,
                                           uint32_t bHi, uint32_t bLo,
                                           int lane, int m0, int n0,
                                           float d[2][4][4]) {
    uint32_t aRow = (uint32_t)(lane & 15);
    uint32_t aK   = (uint32_t)((lane >> 4) << 3);
    uint32_t bRow = (uint32_t)((lane & 7) + ((lane >> 4) << 3));
    uint32_t bK   = (uint32_t)(((lane >> 3) & 1) << 3);
    uint32_t aOff0 = ((uint32_t)(m0 + aRow) * KP + aK) * 2;
    uint32_t aOff1 = aOff0 + 16 * KP * 2;
    uint32_t bOff0 = ((uint32_t)(n0 + bRow) * BST + bK) * 2;
    uint32_t bOff1 = ((uint32_t)(n0 + 16 + bRow) * BST + bK) * 2;

    #pragma unroll 1
    for (int ks = 0; ks < KSTEPS; ks++) {
        uint32_t kb = (uint32_t)ks * 32;   // 16 bf16 = 32 bytes
        uint32_t ah[2][4], al[2][4];
        ldsm4(ah[0][0], ah[0][1], ah[0][2], ah[0][3], aHi + aOff0 + kb);
        ldsm4(ah[1][0], ah[1][1], ah[1][2], ah[1][3], aHi + aOff1 + kb);
        ldsm4(al[0][0], al[0][1], al[0][2], al[0][3], aLo + aOff0 + kb);
        ldsm4(al[1][0], al[1][1], al[1][2], al[1][3], aLo + aOff1 + kb);
        uint32_t bh[4][2], bl[4][2];
        {
            uint32_t r0, r1, r2, r3;
            ldsm4(r0, r1, r2, r3, bHi + bOff0 + kb);
            bh[0][0] = r0; bh[0][1] = r1; bh[1][0] = r2; bh[1][1] = r3;
            ldsm4(r0, r1, r2, r3, bHi + bOff1 + kb);
            bh[2][0] = r0; bh[2][1] = r1; bh[3][0] = r2; bh[3][1] = r3;
            ldsm4(r0, r1, r2, r3, bLo + bOff0 + kb);
            bl[0][0] = r0; bl[0][1] = r1; bl[1][0] = r2; bl[1][1] = r3;
            ldsm4(r0, r1, r2, r3, bLo + bOff1 + kb);
            bl[2][0] = r0; bl[2][1] = r1; bl[3][0] = r2; bl[3][1] = r3;
        }
        #pragma unroll
        for (int mt = 0; mt < 2; mt++)
            #pragma unroll
            for (int nt = 0; nt < 4; nt++) {
                mma16816(d[mt][nt], ah[mt], bh[nt]);
                mma16816(d[mt][nt], ah[mt], bl[nt]);
                mma16816(d[mt][nt], al[mt], bh[nt]);
            }
    }
}

// ---------------- persistent edge MLP via mma.sync bf16 hi/lo split --------
// 148 CTAs x 512 threads (16 warps: 4M x 4N); weights resident in smem.
// dyn smem: A_hi | A_lo | W1_hi | W1_lo | W2_hi | W2_lo  (225280 B)
__global__ __launch_bounds__(MLP_THREADS, 1)
void k_mlp(const float* __restrict__ h,
           const int*   __restrict__ ei,
           const float* __restrict__ ea,
           const float* __restrict__ b1,
           const float* __restrict__ b2,
           int E) {
    extern __shared__ __align__(16) char dsm[];
    __nv_bfloat16* sAhi  = (__nv_bfloat16*)dsm;
    __nv_bfloat16* sAlo  = sAhi + 128 * KP;
    __nv_bfloat16* sB1hi = sAlo + 128 * KP;
    __nv_bfloat16* sB1lo = sB1hi + 128 * KP;
    __nv_bfloat16* sB2hi = sB1lo + 128 * KP;
    __nv_bfloat16* sB2lo = sB2hi + 128 * KP2;
    float* stagef = (float*)dsm;       // epilogue2 staging (reuses A region)

    __shared__ int s_dst[TILE_E], s_src[TILE_E], s_eid[TILE_E];
    __shared__ float s_b1[HH], s_b2[HH];

    int tid = threadIdx.x;
    int wid = tid >> 5;
    int lane = tid & 31;

    int b = blockIdx.x;
    int cs1 = g_ctaStart[1], cs2 = g_ctaStart[2],
        cs3 = g_ctaStart[3], cs4 = g_ctaStart[4];
    if (b >= cs4) return;
    int t;
    if      (b < cs1) t = 0;
    else if (b < cs2) t = 1;
    else if (b < cs3) t = 2;
    else              t = 3;
    int csBase = (t == 0) ? 0 : (t == 1) ? cs1 : (t == 2) ? cs2 : cs3;
    int csEnd  = (t == 0) ? cs1 : (t == 1) ? cs2 : (t == 2) ? cs3 : cs4;
    int myIdx = b - csBase;
    int nCtas = csEnd - csBase;

    int typeOff = g_off[t];
    int typeCnt = g_off[t + 1] - typeOff;
    int nTiles = (typeCnt + TILE_E - 1) / TILE_E;

    // ---- one-time loads: biases + resident weight images ----
    for (int i = tid; i < HH; i += MLP_THREADS) {
        s_b1[i] = b1[t * HH + i];
        s_b2[i] = b2[t * HH + i];
    }
    {
        const int n41 = 128 * KP * 2 / 16;    // 2432 float4 per image
        const float4* w1h = (const float4*)&g_W1b[t][0][0];
        const float4* w1l = (const float4*)&g_W1b[t][1][0];
        float4* d1h = (float4*)sB1hi;
        float4* d1l = (float4*)sB1lo;
        for (int i = tid; i < n41; i += MLP_THREADS) { d1h[i] = w1h[i]; d1l[i] = w1l[i]; }
        const int n42 = 128 * KP2 * 2 / 16;   // 2176 float4 per image
        const float4* w2h = (const float4*)&g_W2b[t][0][0];
        const float4* w2l = (const float4*)&g_W2b[t][1][0];
        float4* d2h = (float4*)sB2hi;
        float4* d2l = (float4*)sB2lo;
        for (int i = tid; i < n42; i += MLP_THREADS) { d2h[i] = w2h[i]; d2l[i] = w2l[i]; }
    }
    __syncthreads();

    uint32_t aHi = smem_u32(sAhi), aLo = smem_u32(sAlo);
    uint32_t b1Hi = smem_u32(sB1hi), b1Lo = smem_u32(sB1lo);
    uint32_t b2Hi = smem_u32(sB2hi), b2Lo = smem_u32(sB2lo);
    int m0 = (wid & 3) * 32;
    int n0 = (wid >> 2) * 32;

    const int* srcp = ei;
    const int* dstp = ei + E;

    // ---- persistent tile loop ----
    for (int tile = myIdx; tile < nTiles; tile += nCtas) {
        int segBase = typeOff + tile * TILE_E;
        int segCnt = typeCnt - tile * TILE_E;
        if (segCnt > TILE_E) segCnt = TILE_E;

        // edge metadata
        for (int i = tid; i < TILE_E; i += MLP_THREADS) {
            if (i < segCnt) {
                int e = g_bucket[segBase + i];
                s_eid[i] = e; s_src[i] = srcp[e]; s_dst[i] = dstp[e];
            } else {
                s_eid[i] = 0; s_src[i] = 0; s_dst[i] = -1;
            }
        }
        __syncthreads();

        // gather x -> bf16 hi/lo into A buffers (warp per edge row, float4)
        for (int i = wid; i < TILE_E; i += 16) {
            bool valid = (i < segCnt);
            int sidx = s_src[i], e = s_eid[i];
            float4 v = valid ? *(const float4*)&h[sidx * HH + lane * 4]
                             : make_float4(0.f, 0.f, 0.f, 0.f);
            uint32_t hw0, lw0, hw1, lw1;
            bf_split2(v.x, v.y, hw0, lw0);
            bf_split2(v.z, v.w, hw1, lw1);
            *(uint2*)&sAhi[i * KP + lane * 4] = make_uint2(hw0, hw1);
            *(uint2*)&sAlo[i * KP + lane * 4] = make_uint2(lw0, lw1);
            if (lane < AA) {
                int j = HH + lane;
                float va = valid ? ea[e * AA + lane] : 0.f;
                __nv_bfloat16 hi, lo; bf_split(va, hi, lo);
                sAhi[i * KP + j] = hi; sAlo[i * KP + j] = lo;
            }
        }
        __syncthreads();

        float d[2][4][4];
        #pragma unroll
        for (int mt = 0; mt < 2; mt++)
            #pragma unroll
            for (int nt = 0; nt < 4; nt++)
                #pragma unroll
                for (int q = 0; q < 4; q++) d[mt][nt][q] = 0.f;

        // ---- GEMM1: K = 144 (9 k-steps) ----
        gemm_split<9, KP>(aHi, aLo, b1Hi, b1Lo, lane, m0, n0, d);
        __syncthreads();

        // epilogue 1: relu(d + b1) -> hi/lo bf16 back into A buffers
        {
            int rbase = m0 + (lane >> 2);
            int cbase = n0 + 2 * (lane & 3);
            #pragma unroll
            for (int mt = 0; mt < 2; mt++) {
                #pragma unroll
                for (int nt = 0; nt < 4; nt++) {
                    int col = cbase + nt * 8;
                    float bb0 = s_b1[col], bb1 = s_b1[col + 1];
                    #pragma unroll
                    for (int half = 0; half < 2; half++) {
                        int r = rbase + mt * 16 + half * 8;
                        float v0 = fmaxf(d[mt][nt][2 * half] + bb0, 0.f);
                        float v1 = fmaxf(d[mt][nt][2 * half + 1] + bb1, 0.f);
                        uint32_t hw, lw;
                        bf_split2(v0, v1, hw, lw);
                        *(uint32_t*)&sAhi[r * KP + col] = hw;
                        *(uint32_t*)&sAlo[r * KP + col] = lw;
                        d[mt][nt][2 * half] = 0.f;
                        d[mt][nt][2 * half + 1] = 0.f;
                    }
                }
            }
        }
        __syncthreads();

        // ---- GEMM2: K = 128 (8 k-steps) ----
        gemm_split<8, KP2>(aHi, aLo, b2Hi, b2Lo, lane, m0, n0, d);
        __syncthreads();   // done reading A before staging overwrites it

        // epilogue 2: stage d + b2 as fp32
        {
            int rbase = m0 + (lane >> 2);
            int cbase = n0 + 2 * (lane & 3);
            #pragma unroll
            for (int mt = 0; mt < 2; mt++) {
                #pragma unroll
                for (int nt = 0; nt < 4; nt++) {
                    int col = cbase + nt * 8;
                    float bb0 = s_b2[col], bb1 = s_b2[col + 1];
                    #pragma unroll
                    for (int half = 0; half < 2; half++) {
                        int r = rbase + mt * 16 + half * 8;
                        stagef[r * SF + col]     = d[mt][nt][2 * half] + bb0;
                        stagef[r * SF + col + 1] = d[mt][nt][2 * half + 1] + bb1;
                    }
                }
            }
        }
        __syncthreads();

        // coalesced scatter-add flush: warp per edge row, red.v4 per lane
        for (int i = wid; i < TILE_E; i += 16) {
            int dstn = s_dst[i];
            if (dstn < 0) continue;
            float4 v = *(float4*)&stagef[i * SF + lane * 4];
            red4(&g_msg[dstn * HH + lane * 4], v);
        }
        __syncthreads();   // stage/A reused next iteration
    }
}

// ---------------- fused GRU cell (f32x2) ----------------
__global__ __launch_bounds__(256, 2)
void k_gru(const float* __restrict__ h,
           const float* __restrict__ b_ih,
           const float* __restrict__ b_hh,
           float* __restrict__ out, int N) {
    extern __shared__ __align__(16) float gdyn[];
    float* s_ms = gdyn;
    float* s_h  = gdyn + HH * GS;
    float* s_wi = gdyn + 2 * HH * GS;
    float* s_wh = s_wi + 2 * 8 * 3 * HH;

    int tid = threadIdx.x;
    int n0 = blockIdx.x * GNS;

    for (int idx = tid; idx < GNS * HH; idx += 256) {
        int i = idx >> 7, k = idx & 127;
        int n = n0 + i;
        float mv = 0.f, hv = 0.f;
        if (n < N) { mv = g_msg[n * HH + k]; hv = h[n * HH + k]; }
        s_ms[k * GS + i] = mv;
        s_h [k * GS + i] = hv;
    }

    int tx = tid & 31;
    int ty = tid >> 5;
    int j = tx * 4;

    u64 ar[4][2], az[4][2], ai[4][2], ah[4][2];
    #pragma unroll
    for (int q = 0; q < 4; q++)
        #pragma unroll
        for (int cp = 0; cp < 2; cp++) {
            ar[q][cp] = 0ull; az[q][cp] = 0ull;
            ai[q][cp] = 0ull; ah[q][cp] = 0ull;
        }

    float4 wi0, wi1, wi2, wh0, wh1, wh2;
    {
        const float4* gi = (const float4*)g_wihT;
        const float4* gh = (const float4*)g_whhT;
        wi0 = gi[tid * 3]; wi1 = gi[tid * 3 + 1]; wi2 = gi[tid * 3 + 2];
        wh0 = gh[tid * 3]; wh1 = gh[tid * 3 + 1]; wh2 = gh[tid * 3 + 2];
        float4* si = (float4*)s_wi;
        float4* sh = (float4*)s_wh;
        si[tid * 3] = wi0; si[tid * 3 + 1] = wi1; si[tid * 3 + 2] = wi2;
        sh[tid * 3] = wh0; sh[tid * 3 + 1] = wh1; sh[tid * 3 + 2] = wh2;
    }
    __syncthreads();

    for (int kt = 0; kt < 16; kt++) {
        int buf = kt & 1;
        if (kt + 1 < 16) {
            const float4* gi = (const float4*)(g_wihT + (kt + 1) * 8 * 3 * HH);
            const float4* gh = (const float4*)(g_whhT + (kt + 1) * 8 * 3 * HH);
            wi0 = gi[tid * 3]; wi1 = gi[tid * 3 + 1]; wi2 = gi[tid * 3 + 2];
            wh0 = gh[tid * 3]; wh1 = gh[tid * 3 + 1]; wh2 = gh[tid * 3 + 2];
        }
        const float* wib = s_wi + buf * (8 * 3 * HH);
        const float* whb = s_wh + buf * (8 * 3 * HH);
        int k0 = kt * 8;
        #pragma unroll
        for (int kk = 0; kk < 8; kk++) {
            int k = k0 + kk;
            u64 md[4], hd[4];
            #pragma unroll
            for (int q = 0; q < 4; q++) {
                md[q] = f2_dup(s_ms[k * GS + ty * 4 + q]);
                hd[q] = f2_dup(s_h [k * GS + ty * 4 + q]);
            }
            const float* wr = &wib[kk * 3 * HH];
            const float* hr = &whb[kk * 3 * HH];
            ulonglong2 wir = *(const ulonglong2*)&wr[j];
            ulonglong2 wiz = *(const ulonglong2*)&wr[HH + j];
            ulonglong2 win = *(const ulonglong2*)&wr[2 * HH + j];
            ulonglong2 whr = *(const ulonglong2*)&hr[j];
            ulonglong2 whz = *(const ulonglong2*)&hr[HH + j];
            ulonglong2 whn = *(const ulonglong2*)&hr[2 * HH + j];
            #pragma unroll
            for (int q = 0; q < 4; q++) {
                f2_fma(ar[q][0], md[q], wir.x); f2_fma(ar[q][0], hd[q], whr.x);
                f2_fma(ar[q][1], md[q], wir.y); f2_fma(ar[q][1], hd[q], whr.y);
                f2_fma(az[q][0], md[q], wiz.x); f2_fma(az[q][0], hd[q], whz.x);
                f2_fma(az[q][1], md[q], wiz.y); f2_fma(az[q][1], hd[q], whz.y);
                f2_fma(ai[q][0], md[q], win.x);
                f2_fma(ai[q][1], md[q], win.y);
                f2_fma(ah[q][0], hd[q], whn.x);
                f2_fma(ah[q][1], hd[q], whn.y);
            }
        }
        if (kt + 1 < 16) {
            float4* si = (float4*)(s_wi + (buf ^ 1) * (8 * 3 * HH));
            float4* sh = (float4*)(s_wh + (buf ^ 1) * (8 * 3 * HH));
            si[tid * 3] = wi0; si[tid * 3 + 1] = wi1; si[tid * 3 + 2] = wi2;
            sh[tid * 3] = wh0; sh[tid * 3 + 1] = wh1; sh[tid * 3 + 2] = wh2;
        }
        __syncthreads();
    }

    #pragma unroll
    for (int q = 0; q < 4; q++) {
        int i = ty * 4 + q;
        int n = n0 + i;
        if (n >= N) continue;
        float sr[4], sz[4], si4[4], sh4[4];
        f2_unpack(ar[q][0], sr[0], sr[1]);  f2_unpack(ar[q][1], sr[2], sr[3]);
        f2_unpack(az[q][0], sz[0], sz[1]);  f2_unpack(az[q][1], sz[2], sz[3]);
        f2_unpack(ai[q][0], si4[0], si4[1]); f2_unpack(ai[q][1], si4[2], si4[3]);
        f2_unpack(ah[q][0], sh4[0], sh4[1]); f2_unpack(ah[q][1], sh4[2], sh4[3]);
        float o[4];
        #pragma unroll
        for (int c = 0; c < 4; c++) {
            int jc = j + c;
            float rg = sr[c] + b_ih[jc] + b_hh[jc];
            rg = 1.f / (1.f + __expf(-rg));
            float zg = sz[c] + b_ih[HH + jc] + b_hh[HH + jc];
            zg = 1.f / (1.f + __expf(-zg));
            float ing = si4[c] + b_ih[2 * HH + jc];
            float hng = sh4[c] + b_hh[2 * HH + jc];
            float ng = tanhf(ing + rg * hng);
            float hv = s_h[jc * GS + i];
            o[c] = (1.f - zg) * ng + zg * hv;
        }
        *(float4*)&out[n * HH + j] = make_float4(o[0], o[1], o[2], o[3]);
    }
}

// ---------------- launch ----------------
extern "C" void kernel_launch(void* const* d_in, const int* in_sizes, int n_in,
                              void* d_out, int out_size) {
    const float* h    = (const float*)d_in[0];
    const int*   ei   = (const int*)  d_in[1];
    const int*   et   = (const int*)  d_in[2];
    const float* ea   = (const float*)d_in[3];
    const float* W1   = (const float*)d_in[4];
    const float* b1   = (const float*)d_in[5];
    const float* W2   = (const float*)d_in[6];
    const float* b2   = (const float*)d_in[7];
    const float* wih  = (const float*)d_in[8];
    const float* whh  = (const float*)d_in[9];
    const float* bih  = (const float*)d_in[10];
    const float* bhh  = (const float*)d_in[11];
    float* out = (float*)d_out;

    int N = in_sizes[0] / HH;   // 50000
    int E = in_sizes[2];        // 800000

    const int mlpSmem = (4 * 128 * KP + 2 * 128 * KP2) * (int)sizeof(__nv_bfloat16); // 225280
    const int gruSmem = (2 * HH * GS + 4 * 8 * 3 * HH) * (int)sizeof(float);
    cudaFuncSetAttribute(k_mlp, cudaFuncAttributeMaxDynamicSharedMemorySize, mlpSmem);
    cudaFuncSetAttribute(k_gru, cudaFuncAttributeMaxDynamicSharedMemorySize, gruSmem);

    k_zero<<<2048, 256>>>();
    k_transpose<<<(HH * 3 * HH + 255) / 256, 256>>>(wih, whh);
    {
        int prepN = TT * 128 * KP + TT * 128 * KP2;
        k_prepW<<<(prepN + 255) / 256, 256>>>(W1, W2);
    }
    k_hist<<<(E + 255) / 256, 256>>>(et, E);
    k_scan<<<1, 1>>>();
    k_scatter<<<(E + 255) / 256, 256>>>(et, E);

    k_mlp<<<MLP_CTAS, MLP_THREADS, mlpSmem>>>(h, ei, ea, b1, b2, E);

    k_gru<<<(N + GNS - 1) / GNS, 256, gruSmem>>>(h, bih, bhh, out, N);
}

// round 11
// speedup vs baseline: 2.4424x; 1.2487x over previous
#include <cuda_runtime.h>
#include <cuda_fp16.h>
#include <cstdint>

// Problem constants (fixed-shape problem)
#define NN 50000
#define HH 128
#define EE 800000
#define AA 16
#define TT 4
#define HA 144            // H + A
#define TILE_E 128
#define KP 152            // fp16 K stride for A / W1 (pad: ldmatrix conflict-free)
#define KP2 136           // fp16 K stride for W2 (K=128 + pad 8)
#define GNS 32            // GRU nodes per CTA
#define GS 33             // padded node stride for GRU staging
#define MLP_CTAS 148
#define MLP_THREADS 512

typedef unsigned long long u64;

// ---------------- f32x2 packed-math helpers (GRU) ----------------
__device__ __forceinline__ u64 f2_pack(float lo, float hi) {
    u64 r;
    asm("mov.b64 %0, {%1,%2};" : "=l"(r)
        : "r"(__float_as_uint(lo)), "r"(__float_as_uint(hi)));
    return r;
}
__device__ __forceinline__ u64 f2_dup(float v) { return f2_pack(v, v); }
__device__ __forceinline__ void f2_fma(u64& d, u64 a, u64 b) {
    asm("fma.rn.f32x2 %0, %1, %2, %0;" : "+l"(d) : "l"(a), "l"(b));
}
__device__ __forceinline__ void f2_unpack(u64 v, float& lo, float& hi) {
    unsigned int l, h;
    asm("mov.b64 {%0,%1}, %2;" : "=r"(l), "=r"(h) : "l"(v));
    lo = __uint_as_float(l); hi = __uint_as_float(h);
}

// ---------------- mma.sync helpers ----------------
__device__ __forceinline__ uint32_t smem_u32(const void* p) {
    uint32_t a;
    asm("{ .reg .u64 t; cvta.to.shared.u64 t, %1; cvt.u32.u64 %0, t; }"
        : "=r"(a) : "l"(p));
    return a;
}
__device__ __forceinline__ void ldsm4(uint32_t& r0, uint32_t& r1,
                                      uint32_t& r2, uint32_t& r3, uint32_t addr) {
    asm volatile("ldmatrix.sync.aligned.m8n8.x4.shared.b16 {%0,%1,%2,%3}, [%4];"
                 : "=r"(r0), "=r"(r1), "=r"(r2), "=r"(r3) : "r"(addr));
}
__device__ __forceinline__ void mma16816(float* d, const uint32_t* a, const uint32_t* b) {
    asm volatile("mma.sync.aligned.m16n8k16.row.col.f32.f16.f16.f32 "
                 "{%0,%1,%2,%3},{%4,%5,%6,%7},{%8,%9},{%0,%1,%2,%3};"
                 : "+f"(d[0]), "+f"(d[1]), "+f"(d[2]), "+f"(d[3])
                 : "r"(a[0]), "r"(a[1]), "r"(a[2]), "r"(a[3]),
                   "r"(b[0]), "r"(b[1]));
}
__device__ __forceinline__ void red2(float* p, float a, float b) {
    asm volatile("red.global.add.v2.f32 [%0], {%1,%2};"
                 :: "l"(p), "f"(a), "f"(b) : "memory");
}

// fp16 hi/lo split of a float
__device__ __forceinline__ void hf_split(float v, __half& hi, __half& lo) {
    hi = __float2half_rn(v);
    lo = __float2half_rn(v - __half2float(hi));
}

// ---------------- device scratch ----------------
__device__ float g_msg[NN * HH];
__device__ int   g_bucket[EE];
__device__ int   g_cnt[TT];
__device__ int   g_cur[TT];
__device__ int   g_off[TT + 1];
__device__ int   g_ctaStart[TT + 1];
__device__ float g_wihT[HH * 3 * HH];
__device__ float g_whhT[HH * 3 * HH];
// fp16 weight images, W^T [N=128][stride] row-major, hi/lo splits
__device__ __align__(16) __half g_W1h[TT][2][128 * KP];
__device__ __align__(16) __half g_W2h[TT][2][128 * KP2];

// ---------------- utility kernels ----------------
__global__ void k_zero() {
    int idx = blockIdx.x * blockDim.x + threadIdx.x;
    int stride = gridDim.x * blockDim.x;
    float4* p = reinterpret_cast<float4*>(g_msg);
    int total4 = NN * HH / 4;
    float4 z = make_float4(0.f, 0.f, 0.f, 0.f);
    for (int i = idx; i < total4; i += stride) p[i] = z;
    if (idx < TT) g_cnt[idx] = 0;
}

__global__ void k_transpose(const float* __restrict__ wih,
                            const float* __restrict__ whh) {
    int idx = blockIdx.x * blockDim.x + threadIdx.x;
    if (idx < HH * 3 * HH) {
        int k = idx / (3 * HH);
        int g = idx % (3 * HH);
        g_wihT[idx] = wih[g * HH + k];
        g_whhT[idx] = whh[g * HH + k];
    }
}

// Build fp16 hi/lo images of W1^T, W2^T as [n][k] row-major.
__global__ void k_prepW(const float* __restrict__ W1, const float* __restrict__ W2) {
    int idx = blockIdx.x * blockDim.x + threadIdx.x;
    const int per1 = 128 * KP;
    const int per2 = 128 * KP2;
    if (idx < TT * per1) {
        int t = idx / per1;
        int rem = idx % per1;
        int n = rem / KP, k = rem % KP;
        float v = (k < HA) ? W1[(t * HA + k) * HH + n] : 0.f;
        __half hi, lo; hf_split(v, hi, lo);
        g_W1h[t][0][n * KP + k] = hi;
        g_W1h[t][1][n * KP + k] = lo;
    } else if (idx < TT * per1 + TT * per2) {
        int j = idx - TT * per1;
        int t = j / per2;
        int rem = j % per2;
        int n = rem / KP2, k = rem % KP2;
        float v = (k < HH) ? W2[(t * HH + k) * HH + n] : 0.f;
        __half hi, lo; hf_split(v, hi, lo);
        g_W2h[t][0][n * KP2 + k] = hi;
        g_W2h[t][1][n * KP2 + k] = lo;
    }
}

__global__ void k_hist(const int* __restrict__ et, int E) {
    __shared__ int c[TT];
    if (threadIdx.x < TT) c[threadIdx.x] = 0;
    __syncthreads();
    int i = blockIdx.x * blockDim.x + threadIdx.x;
    if (i < E) atomicAdd(&c[et[i]], 1);
    __syncthreads();
    if (threadIdx.x < TT && c[threadIdx.x] > 0)
        atomicAdd(&g_cnt[threadIdx.x], c[threadIdx.x]);
}

__global__ void k_scan() {
    int off = 0;
    int nt[TT];
    int tot = 0;
    for (int t = 0; t < TT; t++) {
        g_off[t] = off;
        g_cur[t] = off;
        off += g_cnt[t];
        nt[t] = (g_cnt[t] + TILE_E - 1) / TILE_E;
        tot += nt[t];
    }
    g_off[TT] = off;
    int c[TT]; int used = 0;
    for (int t = 0; t < TT; t++) {
        c[t] = (nt[t] > 0 && tot > 0)
             ? (int)(((long long)MLP_CTAS * nt[t]) / tot) : 0;
        if (nt[t] > 0 && c[t] < 1) c[t] = 1;
        used += c[t];
    }
    while (used > MLP_CTAS) {
        int a = 0;
        for (int t = 1; t < TT; t++) if (c[t] > c[a]) a = t;
        c[a]--; used--;
    }
    int guard = 0;
    while (used < MLP_CTAS && guard < 1000) {
        for (int t = 0; t < TT && used < MLP_CTAS; t++)
            if (nt[t] > 0) { c[t]++; used++; }
        guard++;
        bool any = false;
        for (int t = 0; t < TT; t++) any |= (nt[t] > 0);
        if (!any) break;
    }
    int s = 0;
    for (int t = 0; t < TT; t++) { g_ctaStart[t] = s; s += c[t]; }
    g_ctaStart[TT] = s;
}

__global__ void k_scatter(const int* __restrict__ et, int E) {
    __shared__ int c[TT], base[TT];
    if (threadIdx.x < TT) c[threadIdx.x] = 0;
    __syncthreads();
    int i = blockIdx.x * blockDim.x + threadIdx.x;
    int t = 0, pos = 0;
    bool valid = (i < E);
    if (valid) {
        t = et[i];
        pos = atomicAdd(&c[t], 1);
    }
    __syncthreads();
    if (threadIdx.x < TT)
        base[threadIdx.x] = (c[threadIdx.x] > 0)
            ? atomicAdd(&g_cur[threadIdx.x], c[threadIdx.x]) : 0;
    __syncthreads();
    if (valid) g_bucket[base[t] + pos] = i;
}

// ---------------- fp16 2-product warp GEMM core (32x32 warp tile) ---------
// Warp computes D[32 x 32] at (m0, n0). A row-major [128][KP] fp16 in smem,
// B row-major [128][BST] fp16 ([n][k], k contiguous). Plain ldmatrix both.
template <int KSTEPS, int BST>
__device__ __forceinline__ void gemm2p(uint32_t aBase, uint32_t bHi, uint32_t bLo,
                                       int lane, int m0, int n0,
                                       float d[2][4][4]) {
    uint32_t aRow = (uint32_t)(lane & 15);
    uint32_t aK   = (uint32_t)((lane >> 4) << 3);
    uint32_t bRow = (uint32_t)((lane & 7) + ((lane >> 4) << 3));
    uint32_t bK   = (uint32_t)(((lane >> 3) & 1) << 3);
    uint32_t aOff0 = ((uint32_t)(m0 + aRow) * KP + aK) * 2;
    uint32_t aOff1 = aOff0 + 16 * KP * 2;
    uint32_t bOff0 = ((uint32_t)(n0 + bRow) * BST + bK) * 2;
    uint32_t bOff1 = ((uint32_t)(n0 + 16 + bRow) * BST + bK) * 2;

    #pragma unroll 1
    for (int ks = 0; ks < KSTEPS; ks++) {
        uint32_t kb = (uint32_t)ks * 32;   // 16 fp16 = 32 bytes
        uint32_t ah[2][4];
        ldsm4(ah[0][0], ah[0][1], ah[0][2], ah[0][3], aBase + aOff0 + kb);
        ldsm4(ah[1][0], ah[1][1], ah[1][2], ah[1][3], aBase + aOff1 + kb);
        uint32_t bh[4][2], bl[4][2];
        {
            uint32_t r0, r1, r2, r3;
            ldsm4(r0, r1, r2, r3, bHi + bOff0 + kb);
            bh[0][0] = r0; bh[0][1] = r1; bh[1][0] = r2; bh[1][1] = r3;
            ldsm4(r0, r1, r2, r3, bHi + bOff1 + kb);
            bh[2][0] = r0; bh[2][1] = r1; bh[3][0] = r2; bh[3][1] = r3;
            ldsm4(r0, r1, r2, r3, bLo + bOff0 + kb);
            bl[0][0] = r0; bl[0][1] = r1; bl[1][0] = r2; bl[1][1] = r3;
            ldsm4(r0, r1, r2, r3, bLo + bOff1 + kb);
            bl[2][0] = r0; bl[2][1] = r1; bl[3][0] = r2; bl[3][1] = r3;
        }
        #pragma unroll
        for (int mt = 0; mt < 2; mt++)
            #pragma unroll
            for (int nt = 0; nt < 4; nt++) {
                mma16816(d[mt][nt], ah[mt], bh[nt]);
                mma16816(d[mt][nt], ah[mt], bl[nt]);
            }
    }
}

// ---------------- persistent edge MLP, fp16 2-product, pipelined ----------
// 148 CTAs x 512 threads (16 warps: 4M x 4N); weights resident; A double-buffered;
// next tile's x-gather LDGs issued before GEMM1, stored after it.
// dyn smem: A0 | A1 | W1_hi | W1_lo | W2_hi | W2_lo  (225280 B)
__global__ __launch_bounds__(MLP_THREADS, 1)
void k_mlp(const float* __restrict__ h,
           const int*   __restrict__ ei,
           const float* __restrict__ ea,
           const float* __restrict__ b1,
           const float* __restrict__ b2,
           int E) {
    extern __shared__ __align__(16) char dsm[];
    __half* sA0   = (__half*)dsm;
    __half* sA1   = sA0 + 128 * KP;
    __half* sB1hi = sA1 + 128 * KP;
    __half* sB1lo = sB1hi + 128 * KP;
    __half* sB2hi = sB1lo + 128 * KP;
    __half* sB2lo = sB2hi + 128 * KP2;

    __shared__ int s_src[2][TILE_E], s_dst[2][TILE_E], s_eid[2][TILE_E];

    int tid = threadIdx.x;
    int wid = tid >> 5;
    int lane = tid & 31;

    int b = blockIdx.x;
    int cs1 = g_ctaStart[1], cs2 = g_ctaStart[2],
        cs3 = g_ctaStart[3], cs4 = g_ctaStart[4];
    if (b >= cs4) return;
    int t;
    if      (b < cs1) t = 0;
    else if (b < cs2) t = 1;
    else if (b < cs3) t = 2;
    else              t = 3;
    int csBase = (t == 0) ? 0 : (t == 1) ? cs1 : (t == 2) ? cs2 : cs3;
    int csEnd  = (t == 0) ? cs1 : (t == 1) ? cs2 : (t == 2) ? cs3 : cs4;
    int myIdx = b - csBase;
    int nCtas = csEnd - csBase;

    int typeOff = g_off[t];
    int typeCnt = g_off[t + 1] - typeOff;
    int nTiles = (typeCnt + TILE_E - 1) / TILE_E;

    // per-thread epilogue columns + bias registers
    int m0 = (wid & 3) * 32;
    int n0 = (wid >> 2) * 32;
    int rbase = m0 + (lane >> 2);
    int cbase = n0 + 2 * (lane & 3);
    float rb1[8], rb2[8];
    #pragma unroll
    for (int nt = 0; nt < 4; nt++) {
        rb1[2 * nt]     = b1[t * HH + cbase + nt * 8];
        rb1[2 * nt + 1] = b1[t * HH + cbase + nt * 8 + 1];
        rb2[2 * nt]     = b2[t * HH + cbase + nt * 8];
        rb2[2 * nt + 1] = b2[t * HH + cbase + nt * 8 + 1];
    }

    // ---- one-time load: resident weight images ----
    {
        const int n41 = 128 * KP * 2 / 16;    // 2432 float4 per image
        const float4* w1h = (const float4*)&g_W1h[t][0][0];
        const float4* w1l = (const float4*)&g_W1h[t][1][0];
        float4* d1h = (float4*)sB1hi;
        float4* d1l = (float4*)sB1lo;
        for (int i = tid; i < n41; i += MLP_THREADS) { d1h[i] = w1h[i]; d1l[i] = w1l[i]; }
        const int n42 = 128 * KP2 * 2 / 16;   // 2176 float4 per image
        const float4* w2h = (const float4*)&g_W2h[t][0][0];
        const float4* w2l = (const float4*)&g_W2h[t][1][0];
        float4* d2h = (float4*)sB2hi;
        float4* d2l = (float4*)sB2lo;
        for (int i = tid; i < n42; i += MLP_THREADS) { d2h[i] = w2h[i]; d2l[i] = w2l[i]; }
    }

    uint32_t a0u = smem_u32(sA0), a1u = smem_u32(sA1);
    uint32_t b1Hi = smem_u32(sB1hi), b1Lo = smem_u32(sB1lo);
    uint32_t b2Hi = smem_u32(sB2hi), b2Lo = smem_u32(sB2lo);

    const int* srcp = ei;
    const int* dstp = ei + E;

    // meta loader: fills s_*[sel] for a (possibly out-of-range) tile
    auto load_meta = [&](int tile, int sel) {
        int segBase = typeOff + tile * TILE_E;
        int segCnt = typeCnt - tile * TILE_E;   // may be <=0 or >128
        for (int i = tid; i < TILE_E; i += MLP_THREADS) {
            if (tile < nTiles && i < segCnt) {
                int e = g_bucket[segBase + i];
                s_eid[sel][i] = e; s_src[sel][i] = srcp[e]; s_dst[sel][i] = dstp[e];
            } else {
                s_eid[sel][i] = 0; s_src[sel][i] = 0; s_dst[sel][i] = -1;
            }
        }
    };

    float4 vx[8];   // prefetched x rows (warp-strided)
    auto issue_x = [&](int sel) {
        #pragma unroll
        for (int rr = 0; rr < 8; rr++) {
            int i = wid + rr * 16;
            int sidx = s_src[sel][i];
            vx[rr] = *(const float4*)&h[sidx * HH + lane * 4];
        }
    };
    auto store_x = [&](int sel, __half* dst) {
        #pragma unroll
        for (int rr = 0; rr < 8; rr++) {
            int i = wid + rr * 16;
            __half2 p0 = __float22half2_rn(make_float2(vx[rr].x, vx[rr].y));
            __half2 p1 = __float22half2_rn(make_float2(vx[rr].z, vx[rr].w));
            *(uint2*)&dst[i * KP + lane * 4] =
                make_uint2(*(uint32_t*)&p0, *(uint32_t*)&p1);
        }
        if (lane < AA) {
            #pragma unroll
            for (int rr = 0; rr < 8; rr++) {
                int i = wid + rr * 16;
                int e = s_eid[sel][i];
                dst[i * KP + HH + lane] = __float2half_rn(ea[e * AA + lane]);
            }
        }
    };

    // ---- prologue ----
    int first = myIdx;
    load_meta(first, 0);
    __syncthreads();
    if (first < nTiles) { issue_x(0); store_x(0, sA0); }
    load_meta(first + nCtas, 1);
    __syncthreads();

    // ---- persistent pipelined tile loop ----
    int bufsel = 0;
    for (int tile = first; tile < nTiles; tile += nCtas, bufsel ^= 1) {
        uint32_t Xu = bufsel ? a1u : a0u;
        __half* Y = bufsel ? sA0 : sA1;
        bool hasNext = (tile + nCtas) < nTiles;

        if (hasNext) issue_x(bufsel ^ 1);     // LDGs in flight under GEMM1

        float d[2][4][4];
        #pragma unroll
        for (int mt = 0; mt < 2; mt++)
            #pragma unroll
            for (int nt = 0; nt < 4; nt++)
                #pragma unroll
                for (int q = 0; q < 4; q++) d[mt][nt][q] = 0.f;

        // ---- GEMM1: K = 144 (9 k-steps) ----
        gemm2p<9, KP>(Xu, b1Hi, b1Lo, lane, m0, n0, d);
        __syncthreads();

        // park prefetched x into the other A buffer
        if (hasNext) store_x(bufsel ^ 1, Y);

        // epilogue 1: relu(d + b1) -> fp16 back into X (x is dead)
        {
            __half* X = bufsel ? sA1 : sA0;
            #pragma unroll
            for (int mt = 0; mt < 2; mt++) {
                #pragma unroll
                for (int nt = 0; nt < 4; nt++) {
                    int col = cbase + nt * 8;
                    #pragma unroll
                    for (int half = 0; half < 2; half++) {
                        int r = rbase + mt * 16 + half * 8;
                        float v0 = fmaxf(d[mt][nt][2 * half] + rb1[2 * nt], 0.f);
                        float v1 = fmaxf(d[mt][nt][2 * half + 1] + rb1[2 * nt + 1], 0.f);
                        __half2 p = __float22half2_rn(make_float2(v0, v1));
                        *(uint32_t*)&X[r * KP + col] = *(uint32_t*)&p;
                        d[mt][nt][2 * half] = 0.f;
                        d[mt][nt][2 * half + 1] = 0.f;
                    }
                }
            }
        }
        __syncthreads();

        // ---- GEMM2: K = 128 (8 k-steps) ----
        gemm2p<8, KP2>(Xu, b2Hi, b2Lo, lane, m0, n0, d);

        // scatter directly from fragments (red.v2, no staging)
        #pragma unroll
        for (int mt = 0; mt < 2; mt++) {
            #pragma unroll
            for (int half = 0; half < 2; half++) {
                int r = rbase + mt * 16 + half * 8;
                int dstn = s_dst[bufsel][r];
                if (dstn < 0) continue;
                float* basep = &g_msg[dstn * HH];
                #pragma unroll
                for (int nt = 0; nt < 4; nt++) {
                    int col = cbase + nt * 8;
                    red2(basep + col,
                         d[mt][nt][2 * half] + rb2[2 * nt],
                         d[mt][nt][2 * half + 1] + rb2[2 * nt + 1]);
                }
            }
        }
        __syncthreads();                       // meta[bufsel] free to overwrite

        load_meta(tile + 2 * nCtas, bufsel);   // meta for tile after next
        __syncthreads();
    }
}

// ---------------- fused GRU cell (f32x2) ----------------
__global__ __launch_bounds__(256, 2)
void k_gru(const float* __restrict__ h,
           const float* __restrict__ b_ih,
           const float* __restrict__ b_hh,
           float* __restrict__ out, int N) {
    extern __shared__ __align__(16) float gdyn[];
    float* s_ms = gdyn;
    float* s_h  = gdyn + HH * GS;
    float* s_wi = gdyn + 2 * HH * GS;
    float* s_wh = s_wi + 2 * 8 * 3 * HH;

    int tid = threadIdx.x;
    int n0 = blockIdx.x * GNS;

    for (int idx = tid; idx < GNS * HH; idx += 256) {
        int i = idx >> 7, k = idx & 127;
        int n = n0 + i;
        float mv = 0.f, hv = 0.f;
        if (n < N) { mv = g_msg[n * HH + k]; hv = h[n * HH + k]; }
        s_ms[k * GS + i] = mv;
        s_h [k * GS + i] = hv;
    }

    int tx = tid & 31;
    int ty = tid >> 5;
    int j = tx * 4;

    u64 ar[4][2], az[4][2], ai[4][2], ah[4][2];
    #pragma unroll
    for (int q = 0; q < 4; q++)
        #pragma unroll
        for (int cp = 0; cp < 2; cp++) {
            ar[q][cp] = 0ull; az[q][cp] = 0ull;
            ai[q][cp] = 0ull; ah[q][cp] = 0ull;
        }

    float4 wi0, wi1, wi2, wh0, wh1, wh2;
    {
        const float4* gi = (const float4*)g_wihT;
        const float4* gh = (const float4*)g_whhT;
        wi0 = gi[tid * 3]; wi1 = gi[tid * 3 + 1]; wi2 = gi[tid * 3 + 2];
        wh0 = gh[tid * 3]; wh1 = gh[tid * 3 + 1]; wh2 = gh[tid * 3 + 2];
        float4* si = (float4*)s_wi;
        float4* sh = (float4*)s_wh;
        si[tid * 3] = wi0; si[tid * 3 + 1] = wi1; si[tid * 3 + 2] = wi2;
        sh[tid * 3] = wh0; sh[tid * 3 + 1] = wh1; sh[tid * 3 + 2] = wh2;
    }
    __syncthreads();

    for (int kt = 0; kt < 16; kt++) {
        int buf = kt & 1;
        if (kt + 1 < 16) {
            const float4* gi = (const float4*)(g_wihT + (kt + 1) * 8 * 3 * HH);
            const float4* gh = (const float4*)(g_whhT + (kt + 1) * 8 * 3 * HH);
            wi0 = gi[tid * 3]; wi1 = gi[tid * 3 + 1]; wi2 = gi[tid * 3 + 2];
            wh0 = gh[tid * 3]; wh1 = gh[tid * 3 + 1]; wh2 = gh[tid * 3 + 2];
        }
        const float* wib = s_wi + buf * (8 * 3 * HH);
        const float* whb = s_wh + buf * (8 * 3 * HH);
        int k0 = kt * 8;
        #pragma unroll
        for (int kk = 0; kk < 8; kk++) {
            int k = k0 + kk;
            u64 md[4], hd[4];
            #pragma unroll
            for (int q = 0; q < 4; q++) {
                md[q] = f2_dup(s_ms[k * GS + ty * 4 + q]);
                hd[q] = f2_dup(s_h [k * GS + ty * 4 + q]);
            }
            const float* wr = &wib[kk * 3 * HH];
            const float* hr = &whb[kk * 3 * HH];
            ulonglong2 wir = *(const ulonglong2*)&wr[j];
            ulonglong2 wiz = *(const ulonglong2*)&wr[HH + j];
            ulonglong2 win = *(const ulonglong2*)&wr[2 * HH + j];
            ulonglong2 whr = *(const ulonglong2*)&hr[j];
            ulonglong2 whz = *(const ulonglong2*)&hr[HH + j];
            ulonglong2 whn = *(const ulonglong2*)&hr[2 * HH + j];
            #pragma unroll
            for (int q = 0; q < 4; q++) {
                f2_fma(ar[q][0], md[q], wir.x); f2_fma(ar[q][0], hd[q], whr.x);
                f2_fma(ar[q][1], md[q], wir.y); f2_fma(ar[q][1], hd[q], whr.y);
                f2_fma(az[q][0], md[q], wiz.x); f2_fma(az[q][0], hd[q], whz.x);
                f2_fma(az[q][1], md[q], wiz.y); f2_fma(az[q][1], hd[q], whz.y);
                f2_fma(ai[q][0], md[q], win.x);
                f2_fma(ai[q][1], md[q], win.y);
                f2_fma(ah[q][0], hd[q], whn.x);
                f2_fma(ah[q][1], hd[q], whn.y);
            }
        }
        if (kt + 1 < 16) {
            float4* si = (float4*)(s_wi + (buf ^ 1) * (8 * 3 * HH));
            float4* sh = (float4*)(s_wh + (buf ^ 1) * (8 * 3 * HH));
            si[tid * 3] = wi0; si[tid * 3 + 1] = wi1; si[tid * 3 + 2] = wi2;
            sh[tid * 3] = wh0; sh[tid * 3 + 1] = wh1; sh[tid * 3 + 2] = wh2;
        }
        __syncthreads();
    }

    #pragma unroll
    for (int q = 0; q < 4; q++) {
        int i = ty * 4 + q;
        int n = n0 + i;
        if (n >= N) continue;
        float sr[4], sz[4], si4[4], sh4[4];
        f2_unpack(ar[q][0], sr[0], sr[1]);  f2_unpack(ar[q][1], sr[2], sr[3]);
        f2_unpack(az[q][0], sz[0], sz[1]);  f2_unpack(az[q][1], sz[2], sz[3]);
        f2_unpack(ai[q][0], si4[0], si4[1]); f2_unpack(ai[q][1], si4[2], si4[3]);
        f2_unpack(ah[q][0], sh4[0], sh4[1]); f2_unpack(ah[q][1], sh4[2], sh4[3]);
        float o[4];
        #pragma unroll
        for (int c = 0; c < 4; c++) {
            int jc = j + c;
            float rg = sr[c] + b_ih[jc] + b_hh[jc];
            rg = 1.f / (1.f + __expf(-rg));
            float zg = sz[c] + b_ih[HH + jc] + b_hh[HH + jc];
            zg = 1.f / (1.f + __expf(-zg));
            float ing = si4[c] + b_ih[2 * HH + jc];
            float hng = sh4[c] + b_hh[2 * HH + jc];
            float ng = tanhf(ing + rg * hng);
            float hv = s_h[jc * GS + i];
            o[c] = (1.f - zg) * ng + zg * hv;
        }
        *(float4*)&out[n * HH + j] = make_float4(o[0], o[1], o[2], o[3]);
    }
}

// ---------------- launch ----------------
extern "C" void kernel_launch(void* const* d_in, const int* in_sizes, int n_in,
                              void* d_out, int out_size) {
    const float* h    = (const float*)d_in[0];
    const int*   ei   = (const int*)  d_in[1];
    const int*   et   = (const int*)  d_in[2];
    const float* ea   = (const float*)d_in[3];
    const float* W1   = (const float*)d_in[4];
    const float* b1   = (const float*)d_in[5];
    const float* W2   = (const float*)d_in[6];
    const float* b2   = (const float*)d_in[7];
    const float* wih  = (const float*)d_in[8];
    const float* whh  = (const float*)d_in[9];
    const float* bih  = (const float*)d_in[10];
    const float* bhh  = (const float*)d_in[11];
    float* out = (float*)d_out;

    int N = in_sizes[0] / HH;   // 50000
    int E = in_sizes[2];        // 800000

    const int mlpSmem = (4 * 128 * KP + 2 * 128 * KP2) * (int)sizeof(__half); // 225280
    const int gruSmem = (2 * HH * GS + 4 * 8 * 3 * HH) * (int)sizeof(float);
    cudaFuncSetAttribute(k_mlp, cudaFuncAttributeMaxDynamicSharedMemorySize, mlpSmem);
    cudaFuncSetAttribute(k_gru, cudaFuncAttributeMaxDynamicSharedMemorySize, gruSmem);

    k_zero<<<2048, 256>>>();
    k_transpose<<<(HH * 3 * HH + 255) / 256, 256>>>(wih, whh);
    {
        int prepN = TT * 128 * KP + TT * 128 * KP2;
        k_prepW<<<(prepN + 255) / 256, 256>>>(W1, W2);
    }
    k_hist<<<(E + 255) / 256, 256>>>(et, E);
    k_scan<<<1, 1>>>();
    k_scatter<<<(E + 255) / 256, 256>>>(et, E);

    k_mlp<<<MLP_CTAS, MLP_THREADS, mlpSmem>>>(h, ei, ea, b1, b2, E);

    k_gru<<<(N + GNS - 1) / GNS, 256, gruSmem>>>(h, bih, bhh, out, N);
}

// round 16
// speedup vs baseline: 3.3490x; 1.3712x over previous
#include <cuda_runtime.h>
#include <cuda_fp16.h>
#include <cstdint>

// Problem constants (fixed-shape problem)
#define NN 50000
#define HH 128
#define EE 800000
#define AA 16
#define TT 4
#define HA 144            // H + A
#define TILE_E 128
#define KP 152            // fp16 K stride for A / W1 (pad: ldmatrix conflict-free)
#define KP2 136           // fp16 K stride for W2 (K=128 + pad 8)
#define GAST 264          // fp16 K stride for GRU r/z planes (K=256 + pad 8)
#define GAST2 136         // fp16 K stride for GRU i_n/h_n planes
#define MLP_CTAS 148
#define MLP_THREADS 512
#define GRU_CTAS 148
#define GRU_THREADS 512

// ---------------- mma.sync helpers ----------------
__device__ __forceinline__ uint32_t smem_u32(const void* p) {
    uint32_t a;
    asm("{ .reg .u64 t; cvta.to.shared.u64 t, %1; cvt.u32.u64 %0, t; }"
        : "=r"(a) : "l"(p));
    return a;
}
__device__ __forceinline__ void ldsm4(uint32_t& r0, uint32_t& r1,
                                      uint32_t& r2, uint32_t& r3, uint32_t addr) {
    asm volatile("ldmatrix.sync.aligned.m8n8.x4.shared.b16 {%0,%1,%2,%3}, [%4];"
                 : "=r"(r0), "=r"(r1), "=r"(r2), "=r"(r3) : "r"(addr));
}
__device__ __forceinline__ void mma16816(float* d, const uint32_t* a, const uint32_t* b) {
    asm volatile("mma.sync.aligned.m16n8k16.row.col.f32.f16.f16.f32 "
                 "{%0,%1,%2,%3},{%4,%5,%6,%7},{%8,%9},{%0,%1,%2,%3};"
                 : "+f"(d[0]), "+f"(d[1]), "+f"(d[2]), "+f"(d[3])
                 : "r"(a[0]), "r"(a[1]), "r"(a[2]), "r"(a[3]),
                   "r"(b[0]), "r"(b[1]));
}
__device__ __forceinline__ void red2(float* p, float a, float b) {
    asm volatile("red.global.add.v2.f32 [%0], {%1,%2};"
                 :: "l"(p), "f"(a), "f"(b) : "memory");
}

// fp16 hi/lo split of a float
__device__ __forceinline__ void hf_split(float v, __half& hi, __half& lo) {
    hi = __float2half_rn(v);
    lo = __float2half_rn(v - __half2float(hi));
}

// ---------------- device scratch ----------------
__device__ float g_msg[NN * HH];
__device__ float g_gates[4][NN * HH];     // r_sum, z_sum, i_n, h_n planes
__device__ int   g_bucket[EE];
__device__ int   g_cnt[TT];
__device__ int   g_cur[TT];
__device__ int   g_off[TT + 1];
__device__ int   g_ctaStart[TT + 1];
// fp16 weight images, [N rows][K stride] row-major, hi/lo splits
__device__ __align__(16) __half g_W1h[TT][2][128 * KP];
__device__ __align__(16) __half g_W2h[TT][2][128 * KP2];
__device__ __align__(16) __half g_WgruHi[4][128 * GAST];
__device__ __align__(16) __half g_WgruLo[4][128 * GAST];

// ---------------- utility kernels ----------------
__global__ void k_zero() {
    int idx = blockIdx.x * blockDim.x + threadIdx.x;
    int stride = gridDim.x * blockDim.x;
    float4* p = reinterpret_cast<float4*>(g_msg);
    int total4 = NN * HH / 4;
    float4 z = make_float4(0.f, 0.f, 0.f, 0.f);
    for (int i = idx; i < total4; i += stride) p[i] = z;
    if (idx < TT) g_cnt[idx] = 0;
}

// Build fp16 hi/lo images of W1^T, W2^T, and the 4 GRU gate planes.
__global__ void k_prepW(const float* __restrict__ W1, const float* __restrict__ W2,
                        const float* __restrict__ wih, const float* __restrict__ whh) {
    int idx = blockIdx.x * blockDim.x + threadIdx.x;
    const int per1 = 128 * KP;
    const int per2 = 128 * KP2;
    const int base2 = TT * per1;
    const int base3 = base2 + TT * per2;
    const int gruRZ = 2 * 128 * GAST;          // planes 0,1
    const int base4 = base3 + gruRZ;
    const int gruNH = 2 * 128 * GAST2;         // planes 2,3
    if (idx < base2) {
        int t = idx / per1;
        int rem = idx % per1;
        int n = rem / KP, k = rem % KP;
        float v = (k < HA) ? W1[(t * HA + k) * HH + n] : 0.f;
        __half hi, lo; hf_split(v, hi, lo);
        g_W1h[t][0][n * KP + k] = hi;
        g_W1h[t][1][n * KP + k] = lo;
    } else if (idx < base3) {
        int j = idx - base2;
        int t = j / per2;
        int rem = j % per2;
        int n = rem / KP2, k = rem % KP2;
        float v = (k < HH) ? W2[(t * HH + k) * HH + n] : 0.f;
        __half hi, lo; hf_split(v, hi, lo);
        g_W2h[t][0][n * KP2 + k] = hi;
        g_W2h[t][1][n * KP2 + k] = lo;
    } else if (idx < base4) {
        int j = idx - base3;
        int plane = j / (128 * GAST);          // 0 = r, 1 = z
        int rem = j % (128 * GAST);
        int n = rem / GAST, k = rem % GAST;
        float v = 0.f;
        if (k < 128)        v = wih[(plane * 128 + n) * HH + k];
        else if (k < 256)   v = whh[(plane * 128 + n) * HH + (k - 128)];
        __half hi, lo; hf_split(v, hi, lo);
        g_WgruHi[plane][n * GAST + k] = hi;
        g_WgruLo[plane][n * GAST + k] = lo;
    } else if (idx < base4 + gruNH) {
        int j = idx - base4;
        int plane = 2 + j / (128 * GAST2);     // 2 = i_n, 3 = h_n
        int rem = j % (128 * GAST2);
        int n = rem / GAST2, k = rem % GAST2;
        float v = 0.f;
        if (k < 128)
            v = (plane == 2) ? wih[(256 + n) * HH + k] : whh[(256 + n) * HH + k];
        __half hi, lo; hf_split(v, hi, lo);
        g_WgruHi[plane][n * GAST2 + k] = hi;
        g_WgruLo[plane][n * GAST2 + k] = lo;
    }
}

__global__ void k_hist(const int* __restrict__ et, int E) {
    __shared__ int c[TT];
    if (threadIdx.x < TT) c[threadIdx.x] = 0;
    __syncthreads();
    int i = blockIdx.x * blockDim.x + threadIdx.x;
    if (i < E) atomicAdd(&c[et[i]], 1);
    __syncthreads();
    if (threadIdx.x < TT && c[threadIdx.x] > 0)
        atomicAdd(&g_cnt[threadIdx.x], c[threadIdx.x]);
}

__global__ void k_scan() {
    int off = 0;
    int nt[TT];
    int tot = 0;
    for (int t = 0; t < TT; t++) {
        g_off[t] = off;
        g_cur[t] = off;
        off += g_cnt[t];
        nt[t] = (g_cnt[t] + TILE_E - 1) / TILE_E;
        tot += nt[t];
    }
    g_off[TT] = off;
    int c[TT]; int used = 0;
    for (int t = 0; t < TT; t++) {
        c[t] = (nt[t] > 0 && tot > 0)
             ? (int)(((long long)MLP_CTAS * nt[t]) / tot) : 0;
        if (nt[t] > 0 && c[t] < 1) c[t] = 1;
        used += c[t];
    }
    while (used > MLP_CTAS) {
        int a = 0;
        for (int t = 1; t < TT; t++) if (c[t] > c[a]) a = t;
        c[a]--; used--;
    }
    int guard = 0;
    while (used < MLP_CTAS && guard < 1000) {
        for (int t = 0; t < TT && used < MLP_CTAS; t++)
            if (nt[t] > 0) { c[t]++; used++; }
        guard++;
        bool any = false;
        for (int t = 0; t < TT; t++) any |= (nt[t] > 0);
        if (!any) break;
    }
    int s = 0;
    for (int t = 0; t < TT; t++) { g_ctaStart[t] = s; s += c[t]; }
    g_ctaStart[TT] = s;
}

__global__ void k_scatter(const int* __restrict__ et, int E) {
    __shared__ int c[TT], base[TT];
    if (threadIdx.x < TT) c[threadIdx.x] = 0;
    __syncthreads();
    int i = blockIdx.x * blockDim.x + threadIdx.x;
    int t = 0, pos = 0;
    bool valid = (i < E);
    if (valid) {
        t = et[i];
        pos = atomicAdd(&c[t], 1);
    }
    __syncthreads();
    if (threadIdx.x < TT)
        base[threadIdx.x] = (c[threadIdx.x] > 0)
            ? atomicAdd(&g_cur[threadIdx.x], c[threadIdx.x]) : 0;
    __syncthreads();
    if (valid) g_bucket[base[t] + pos] = i;
}

// ---------------- fp16 warp GEMM core (32x32 warp tile) -------------------
// Warp computes D[32 x 32] at (m0, n0). A row-major [M][AST] fp16 in smem,
// B row-major [N][BST] fp16 ([n][k], k contiguous). NPROD: 1 = hi only,
// 2 = hi + lo weight products.
template <int KSTEPS, int AST, int BST, int NPROD>
__device__ __forceinline__ void gemm2p(uint32_t aBase, uint32_t bHi, uint32_t bLo,
                                       int lane, int m0, int n0,
                                       float d[2][4][4]) {
    uint32_t aRow = (uint32_t)(lane & 15);
    uint32_t aK   = (uint32_t)((lane >> 4) << 3);
    uint32_t bRow = (uint32_t)((lane & 7) + ((lane >> 4) << 3));
    uint32_t bK   = (uint32_t)(((lane >> 3) & 1) << 3);
    uint32_t aOff0 = ((uint32_t)(m0 + aRow) * AST + aK) * 2;
    uint32_t aOff1 = aOff0 + 16 * AST * 2;
    uint32_t bOff0 = ((uint32_t)(n0 + bRow) * BST + bK) * 2;
    uint32_t bOff1 = ((uint32_t)(n0 + 16 + bRow) * BST + bK) * 2;

    #pragma unroll 1
    for (int ks = 0; ks < KSTEPS; ks++) {
        uint32_t kb = (uint32_t)ks * 32;   // 16 fp16 = 32 bytes
        uint32_t ah[2][4];
        ldsm4(ah[0][0], ah[0][1], ah[0][2], ah[0][3], aBase + aOff0 + kb);
        ldsm4(ah[1][0], ah[1][1], ah[1][2], ah[1][3], aBase + aOff1 + kb);
        uint32_t bh[4][2], bl[4][2];
        {
            uint32_t r0, r1, r2, r3;
            ldsm4(r0, r1, r2, r3, bHi + bOff0 + kb);
            bh[0][0] = r0; bh[0][1] = r1; bh[1][0] = r2; bh[1][1] = r3;
            ldsm4(r0, r1, r2, r3, bHi + bOff1 + kb);
            bh[2][0] = r0; bh[2][1] = r1; bh[3][0] = r2; bh[3][1] = r3;
            if (NPROD == 2) {
                ldsm4(r0, r1, r2, r3, bLo + bOff0 + kb);
                bl[0][0] = r0; bl[0][1] = r1; bl[1][0] = r2; bl[1][1] = r3;
                ldsm4(r0, r1, r2, r3, bLo + bOff1 + kb);
                bl[2][0] = r0; bl[2][1] = r1; bl[3][0] = r2; bl[3][1] = r3;
            }
        }
        #pragma unroll
        for (int mt = 0; mt < 2; mt++)
            #pragma unroll
            for (int nt = 0; nt < 4; nt++) {
                mma16816(d[mt][nt], ah[mt], bh[nt]);
                if (NPROD == 2) mma16816(d[mt][nt], ah[mt], bl[nt]);
            }
    }
}

// ---------------- persistent edge MLP, fp16, pipelined --------------------
// GEMM1: W split 2-product (K=144). GEMM2: hi-only (K=128).
// dyn smem: A0 | A1 | W1_hi | W1_lo | W2_hi  (190464 B)
__global__ __launch_bounds__(MLP_THREADS, 1)
void k_mlp(const float* __restrict__ h,
           const int*   __restrict__ ei,
           const float* __restrict__ ea,
           const float* __restrict__ b1,
           const float* __restrict__ b2,
           int E) {
    extern __shared__ __align__(16) char dsm[];
    __half* sA0   = (__half*)dsm;
    __half* sA1   = sA0 + 128 * KP;
    __half* sB1hi = sA1 + 128 * KP;
    __half* sB1lo = sB1hi + 128 * KP;
    __half* sB2hi = sB1lo + 128 * KP;

    __shared__ int s_src[2][TILE_E], s_dst[2][TILE_E], s_eid[2][TILE_E];

    int tid = threadIdx.x;
    int wid = tid >> 5;
    int lane = tid & 31;

    int b = blockIdx.x;
    int cs1 = g_ctaStart[1], cs2 = g_ctaStart[2],
        cs3 = g_ctaStart[3], cs4 = g_ctaStart[4];
    if (b >= cs4) return;
    int t;
    if      (b < cs1) t = 0;
    else if (b < cs2) t = 1;
    else if (b < cs3) t = 2;
    else              t = 3;
    int csBase = (t == 0) ? 0 : (t == 1) ? cs1 : (t == 2) ? cs2 : cs3;
    int csEnd  = (t == 0) ? cs1 : (t == 1) ? cs2 : (t == 2) ? cs3 : cs4;
    int myIdx = b - csBase;
    int nCtas = csEnd - csBase;

    int typeOff = g_off[t];
    int typeCnt = g_off[t + 1] - typeOff;
    int nTiles = (typeCnt + TILE_E - 1) / TILE_E;

    int m0 = (wid & 3) * 32;
    int n0 = (wid >> 2) * 32;
    int rbase = m0 + (lane >> 2);
    int cbase = n0 + 2 * (lane & 3);
    float rb1[8], rb2[8];
    #pragma unroll
    for (int nt = 0; nt < 4; nt++) {
        rb1[2 * nt]     = b1[t * HH + cbase + nt * 8];
        rb1[2 * nt + 1] = b1[t * HH + cbase + nt * 8 + 1];
        rb2[2 * nt]     = b2[t * HH + cbase + nt * 8];
        rb2[2 * nt + 1] = b2[t * HH + cbase + nt * 8 + 1];
    }

    // ---- one-time load: resident weight images ----
    {
        const int n41 = 128 * KP * 2 / 16;
        const float4* w1h = (const float4*)&g_W1h[t][0][0];
        const float4* w1l = (const float4*)&g_W1h[t][1][0];
        float4* d1h = (float4*)sB1hi;
        float4* d1l = (float4*)sB1lo;
        for (int i = tid; i < n41; i += MLP_THREADS) { d1h[i] = w1h[i]; d1l[i] = w1l[i]; }
        const int n42 = 128 * KP2 * 2 / 16;
        const float4* w2h = (const float4*)&g_W2h[t][0][0];
        float4* d2h = (float4*)sB2hi;
        for (int i = tid; i < n42; i += MLP_THREADS) { d2h[i] = w2h[i]; }
    }

    uint32_t a0u = smem_u32(sA0), a1u = smem_u32(sA1);
    uint32_t b1Hi = smem_u32(sB1hi), b1Lo = smem_u32(sB1lo);
    uint32_t b2Hi = smem_u32(sB2hi);

    const int* srcp = ei;
    const int* dstp = ei + E;

    auto load_meta = [&](int tile, int sel) {
        int segBase = typeOff + tile * TILE_E;
        int segCnt = typeCnt - tile * TILE_E;
        for (int i = tid; i < TILE_E; i += MLP_THREADS) {
            if (tile < nTiles && i < segCnt) {
                int e = g_bucket[segBase + i];
                s_eid[sel][i] = e; s_src[sel][i] = srcp[e]; s_dst[sel][i] = dstp[e];
            } else {
                s_eid[sel][i] = 0; s_src[sel][i] = 0; s_dst[sel][i] = -1;
            }
        }
    };

    float4 vx[8];
    auto issue_x = [&](int sel) {
        #pragma unroll
        for (int rr = 0; rr < 8; rr++) {
            int i = wid + rr * 16;
            int sidx = s_src[sel][i];
            vx[rr] = *(const float4*)&h[sidx * HH + lane * 4];
        }
    };
    auto store_x = [&](int sel, __half* dst) {
        #pragma unroll
        for (int rr = 0; rr < 8; rr++) {
            int i = wid + rr * 16;
            __half2 p0 = __float22half2_rn(make_float2(vx[rr].x, vx[rr].y));
            __half2 p1 = __float22half2_rn(make_float2(vx[rr].z, vx[rr].w));
            *(uint2*)&dst[i * KP + lane * 4] =
                make_uint2(*(uint32_t*)&p0, *(uint32_t*)&p1);
        }
        if (lane < AA) {
            #pragma unroll
            for (int rr = 0; rr < 8; rr++) {
                int i = wid + rr * 16;
                int e = s_eid[sel][i];
                dst[i * KP + HH + lane] = __float2half_rn(ea[e * AA + lane]);
            }
        }
    };

    int first = myIdx;
    load_meta(first, 0);
    __syncthreads();
    if (first < nTiles) { issue_x(0); store_x(0, sA0); }
    load_meta(first + nCtas, 1);
    __syncthreads();

    int bufsel = 0;
    for (int tile = first; tile < nTiles; tile += nCtas, bufsel ^= 1) {
        uint32_t Xu = bufsel ? a1u : a0u;
        __half* Y = bufsel ? sA0 : sA1;
        bool hasNext = (tile + nCtas) < nTiles;

        if (hasNext) issue_x(bufsel ^ 1);

        float d[2][4][4];
        #pragma unroll
        for (int mt = 0; mt < 2; mt++)
            #pragma unroll
            for (int nt = 0; nt < 4; nt++)
                #pragma unroll
                for (int q = 0; q < 4; q++) d[mt][nt][q] = 0.f;

        // ---- GEMM1: K = 144, W split 2-product ----
        gemm2p<9, KP, KP, 2>(Xu, b1Hi, b1Lo, lane, m0, n0, d);
        __syncthreads();

        if (hasNext) store_x(bufsel ^ 1, Y);

        // epilogue 1: relu(d + b1) -> fp16 back into X
        {
            __half* X = bufsel ? sA1 : sA0;
            #pragma unroll
            for (int mt = 0; mt < 2; mt++) {
                #pragma unroll
                for (int nt = 0; nt < 4; nt++) {
                    int col = cbase + nt * 8;
                    #pragma unroll
                    for (int half = 0; half < 2; half++) {
                        int r = rbase + mt * 16 + half * 8;
                        float v0 = fmaxf(d[mt][nt][2 * half] + rb1[2 * nt], 0.f);
                        float v1 = fmaxf(d[mt][nt][2 * half + 1] + rb1[2 * nt + 1], 0.f);
                        __half2 p = __float22half2_rn(make_float2(v0, v1));
                        *(uint32_t*)&X[r * KP + col] = *(uint32_t*)&p;
                        d[mt][nt][2 * half] = 0.f;
                        d[mt][nt][2 * half + 1] = 0.f;
                    }
                }
            }
        }
        __syncthreads();

        // ---- GEMM2: K = 128, hi-only ----
        gemm2p<8, KP, KP2, 1>(Xu, b2Hi, b2Hi, lane, m0, n0, d);

        // scatter directly from fragments
        #pragma unroll
        for (int mt = 0; mt < 2; mt++) {
            #pragma unroll
            for (int half = 0; half < 2; half++) {
                int r = rbase + mt * 16 + half * 8;
                int dstn = s_dst[bufsel][r];
                if (dstn < 0) continue;
                float* basep = &g_msg[dstn * HH];
                #pragma unroll
                for (int nt = 0; nt < 4; nt++) {
                    int col = cbase + nt * 8;
                    red2(basep + col,
                         d[mt][nt][2 * half] + rb2[2 * nt],
                         d[mt][nt][2 * half + 1] + rb2[2 * nt + 1]);
                }
            }
        }
        __syncthreads();

        load_meta(tile + 2 * nCtas, bufsel);
        __syncthreads();
    }
}

// ---------------- GRU gate GEMMs on tensor cores --------------------------
// 148 persistent CTAs: planes r(49), z(49), i_n(25), h_n(25).
// r/z: A = [msg|h] K=256; i_n: A = msg K=128; h_n: A = h K=128.
// Weights fp16 hi/lo resident; planes written fp32 to g_gates.
__global__ __launch_bounds__(GRU_THREADS, 1)
void k_grugemm(const float* __restrict__ h, int N) {
    extern __shared__ __align__(16) char dsm[];
    __half* sA  = (__half*)dsm;                 // [128][GAST]
    __half* sWh = sA + 128 * GAST;
    __half* sWl = sWh + 128 * GAST;

    int tid = threadIdx.x;
    int wid = tid >> 5;
    int lane = tid & 31;

    int b = blockIdx.x;
    int plane, base, cnt;
    if      (b < 49)  { plane = 0; base = 0;   cnt = 49; }
    else if (b < 98)  { plane = 1; base = 49;  cnt = 49; }
    else if (b < 123) { plane = 2; base = 98;  cnt = 25; }
    else              { plane = 3; base = 123; cnt = 25; }
    int myIdx = b - base;
    bool wide = (plane < 2);
    int ast = wide ? GAST : GAST2;

    // resident weights
    {
        int n4 = 128 * ast / 8;
        const float4* wh = (const float4*)&g_WgruHi[plane][0];
        const float4* wl = (const float4*)&g_WgruLo[plane][0];
        float4* dh = (float4*)sWh;
        float4* dl = (float4*)sWl;
        for (int i = tid; i < n4; i += GRU_THREADS) { dh[i] = wh[i]; dl[i] = wl[i]; }
    }
    __syncthreads();

    uint32_t aU = smem_u32(sA);
    uint32_t whU = smem_u32(sWh), wlU = smem_u32(sWl);
    int m0 = (wid & 3) * 32;
    int n0 = (wid >> 2) * 32;
    int rbase = m0 + (lane >> 2);
    int cbase = n0 + 2 * (lane & 3);

    float* gout = &g_gates[plane][0];
    int nTiles = (N + 127) / 128;

    for (int tile = myIdx; tile < nTiles; tile += cnt) {
        int nodeBase = tile * 128;

        // stage A
        if (wide) {
            for (int q = tid; q < 128 * 32; q += GRU_THREADS) {
                int node = q >> 5, c = (q & 31) * 4;
                int n = nodeBase + node;
                float4 mv, hv;
                if (n < N) {
                    mv = *(const float4*)&g_msg[n * HH + c];
                    hv = *(const float4*)&h[n * HH + c];
                } else {
                    mv = make_float4(0.f, 0.f, 0.f, 0.f); hv = mv;
                }
                __half2 m0p = __float22half2_rn(make_float2(mv.x, mv.y));
                __half2 m1p = __float22half2_rn(make_float2(mv.z, mv.w));
                __half2 h0p = __float22half2_rn(make_float2(hv.x, hv.y));
                __half2 h1p = __float22half2_rn(make_float2(hv.z, hv.w));
                *(uint2*)&sA[node * GAST + c] =
                    make_uint2(*(uint32_t*)&m0p, *(uint32_t*)&m1p);
                *(uint2*)&sA[node * GAST + 128 + c] =
                    make_uint2(*(uint32_t*)&h0p, *(uint32_t*)&h1p);
            }
        } else {
            const float* src = (plane == 2) ? &g_msg[0] : h;
            for (int q = tid; q < 128 * 32; q += GRU_THREADS) {
                int node = q >> 5, c = (q & 31) * 4;
                int n = nodeBase + node;
                float4 v = (n < N) ? *(const float4*)&src[n * HH + c]
                                   : make_float4(0.f, 0.f, 0.f, 0.f);
                __half2 p0 = __float22half2_rn(make_float2(v.x, v.y));
                __half2 p1 = __float22half2_rn(make_float2(v.z, v.w));
                *(uint2*)&sA[node * GAST2 + c] =
                    make_uint2(*(uint32_t*)&p0, *(uint32_t*)&p1);
            }
        }
        __syncthreads();

        float d[2][4][4];
        #pragma unroll
        for (int mt = 0; mt < 2; mt++)
            #pragma unroll
            for (int nt = 0; nt < 4; nt++)
                #pragma unroll
                for (int q = 0; q < 4; q++) d[mt][nt][q] = 0.f;

        if (wide) gemm2p<16, GAST, GAST, 2>(aU, whU, wlU, lane, m0, n0, d);
        else      gemm2p<8, GAST2, GAST2, 2>(aU, whU, wlU, lane, m0, n0, d);

        // store plane (fp32)
        #pragma unroll
        for (int mt = 0; mt < 2; mt++) {
            #pragma unroll
            for (int half = 0; half < 2; half++) {
                int r = rbase + mt * 16 + half * 8;
                int n = nodeBase + r;
                if (n >= N) continue;
                #pragma unroll
                for (int nt = 0; nt < 4; nt++) {
                    int col = cbase + nt * 8;
                    *(float2*)&gout[n * HH + col] =
                        make_float2(d[mt][nt][2 * half], d[mt][nt][2 * half + 1]);
                }
            }
        }
        __syncthreads();
    }
}

// ---------------- GRU elementwise epilogue ---------------------------------
__global__ void k_gruepi(const float* __restrict__ h,
                         const float* __restrict__ b_ih,
                         const float* __restrict__ b_hh,
                         float* __restrict__ out, int N) {
    int idx = blockIdx.x * blockDim.x + threadIdx.x;
    if (idx >= N * 32) return;
    int n = idx >> 5;
    int cg = (idx & 31) * 4;
    float4 rs = *(const float4*)&g_gates[0][n * HH + cg];
    float4 zs = *(const float4*)&g_gates[1][n * HH + cg];
    float4 is = *(const float4*)&g_gates[2][n * HH + cg];
    float4 hs = *(const float4*)&g_gates[3][n * HH + cg];
    float4 hv = *(const float4*)&h[n * HH + cg];
    float o[4];
    float rr[4] = {rs.x, rs.y, rs.z, rs.w};
    float zz[4] = {zs.x, zs.y, zs.z, zs.w};
    float ii[4] = {is.x, is.y, is.z, is.w};
    float hh2[4] = {hs.x, hs.y, hs.z, hs.w};
    float hvv[4] = {hv.x, hv.y, hv.z, hv.w};
    #pragma unroll
    for (int c = 0; c < 4; c++) {
        int jc = cg + c;
        float rg = rr[c] + b_ih[jc] + b_hh[jc];
        rg = 1.f / (1.f + __expf(-rg));
        float zg = zz[c] + b_ih[HH + jc] + b_hh[HH + jc];
        zg = 1.f / (1.f + __expf(-zg));
        float ng = tanhf(ii[c] + b_ih[2 * HH + jc] + rg * (hh2[c] + b_hh[2 * HH + jc]));
        o[c] = (1.f - zg) * ng + zg * hvv[c];
    }
    *(float4*)&out[n * HH + cg] = make_float4(o[0], o[1], o[2], o[3]);
}

// ---------------- launch ----------------
extern "C" void kernel_launch(void* const* d_in, const int* in_sizes, int n_in,
                              void* d_out, int out_size) {
    const float* h    = (const float*)d_in[0];
    const int*   ei   = (const int*)  d_in[1];
    const int*   et   = (const int*)  d_in[2];
    const float* ea   = (const float*)d_in[3];
    const float* W1   = (const float*)d_in[4];
    const float* b1   = (const float*)d_in[5];
    const float* W2   = (const float*)d_in[6];
    const float* b2   = (const float*)d_in[7];
    const float* wih  = (const float*)d_in[8];
    const float* whh  = (const float*)d_in[9];
    const float* bih  = (const float*)d_in[10];
    const float* bhh  = (const float*)d_in[11];
    float* out = (float*)d_out;

    int N = in_sizes[0] / HH;   // 50000
    int E = in_sizes[2];        // 800000

    const int mlpSmem = (4 * 128 * KP + 128 * KP2) * (int)sizeof(__half);   // 190464
    const int gruSmem = 3 * 128 * GAST * (int)sizeof(__half);               // 202752
    cudaFuncSetAttribute(k_mlp, cudaFuncAttributeMaxDynamicSharedMemorySize, mlpSmem);
    cudaFuncSetAttribute(k_grugemm, cudaFuncAttributeMaxDynamicSharedMemorySize, gruSmem);

    k_zero<<<2048, 256>>>();
    {
        int prepN = TT * 128 * KP + TT * 128 * KP2
                  + 2 * 128 * GAST + 2 * 128 * GAST2;
        k_prepW<<<(prepN + 255) / 256, 256>>>(W1, W2, wih, whh);
    }
    k_hist<<<(E + 255) / 256, 256>>>(et, E);
    k_scan<<<1, 1>>>();
    k_scatter<<<(E + 255) / 256, 256>>>(et, E);

    k_mlp<<<MLP_CTAS, MLP_THREADS, mlpSmem>>>(h, ei, ea, b1, b2, E);

    k_grugemm<<<GRU_CTAS, GRU_THREADS, gruSmem>>>(h, N);
    k_gruepi<<<(N * 32 + 255) / 256, 256>>>(h, bih, bhh, out, N);
}